// round 7
// baseline (speedup 1.0000x reference)
#include <cuda_runtime.h>
#include <cuda_bf16.h>
#include <mma.h>
#include <math.h>
#include <stdint.h>

using namespace nvcuda;

// ---------------- problem constants ----------------
#define BATCH 8
#define NA    1614
#define TOPN  6
#define OUTP  224
#define GN    1568              // 8*196 px
#define GNP   1664              // padded N (13 tiles * 128)
#define GK    18432             // 2048*9
#define KS1   24                // conv1 K-splits
#define NCH1  48                // chunks of k=16 per split (1152/24)
#define C2S   16
#define C3S   16

#define OFF_COORDS 7225344
#define OFF_PROB   7225536
#define OFF_IDX    7225584

// smem element offsets (bf16 elems), ldm 24 (16 used + 8 pad)
#define AH_O  0
#define AL_O  3072
#define BH_O  6144
#define BL_O  9216
#define BUFS  12288
#define DYNSMEM (2 * BUFS * 2)      // 49152 bytes

// ---------------- scratch globals ----------------
__device__ __nv_bfloat16 g_wAh[128 * 9 * 2048];   // weights [oc][t9][ic] hi
__device__ __nv_bfloat16 g_wAl[128 * 9 * 2048];   // lo
__device__ __nv_bfloat16 g_rTh[8 * 196 * 2048];   // rpn NHWC [b][p][ic] hi
__device__ __nv_bfloat16 g_rTl[8 * 196 * 2048];   // lo
__device__ float g_part[KS1][128][GNP];
__device__ float g_d1[BATCH][128][196];
__device__ float g_d2[BATCH][128][49];
__device__ float g_d3[BATCH][128][16];
__device__ float g_p2[C2S][BATCH][128][49];
__device__ float g_p3[C3S][BATCH][128][16];
__device__ float g_scores[BATCH][NA];
__device__ int   g_boxes[BATCH][TOPN][4];

// ---------------- merged prep: blocks [0,1024) = weights, [1024,1536) = rpn ----------------
__global__ __launch_bounds__(256) void prep_all(const float* __restrict__ wd1,
                                                const float* __restrict__ rpn) {
    if (blockIdx.x < 1024) {
        __shared__ float w[2304];
        const int oc = blockIdx.x >> 3;
        const int ic0 = (blockIdx.x & 7) * 256;
        const float* src = wd1 + (size_t)oc * GK + (size_t)ic0 * 9;
        for (int i = threadIdx.x; i < 2304; i += 256) w[i] = src[i];
        __syncthreads();
        for (int i = threadIdx.x; i < 2304; i += 256) {
            int t9 = i >> 8, ic = i & 255;
            float a = w[ic * 9 + t9];
            __nv_bfloat16 hi = __float2bfloat16(a);
            __nv_bfloat16 lo = __float2bfloat16(a - __bfloat162float(hi));
            int o = (oc * 9 + t9) * 2048 + ic0 + ic;
            g_wAh[o] = hi; g_wAl[o] = lo;
        }
    } else {
        __shared__ float sm_[32][197];
        const int r = blockIdx.x - 1024;
        const int b = r >> 6;
        const int ic0 = (r & 63) * 32;
        const float* src = rpn + ((size_t)b * 2048 + ic0) * 196;
        for (int i = threadIdx.x; i < 32 * 196; i += 256) {
            int ic = i / 196, p = i - ic * 196;
            sm_[ic][p] = src[ic * 196 + p];
        }
        __syncthreads();
        for (int i = threadIdx.x; i < 32 * 196; i += 256) {
            int p = i >> 5, ic = i & 31;
            float a = sm_[ic][p];
            __nv_bfloat16 hi = __float2bfloat16(a);
            __nv_bfloat16 lo = __float2bfloat16(a - __bfloat162float(hi));
            int o = (b * 196 + p) * 2048 + ic0 + ic;
            g_rTh[o] = hi; g_rTl[o] = lo;
        }
    }
}

// ---------------- conv1 via wmma bf16 hi/lo split ----------------
// grid (13 n-tiles, 24 k-splits), 128 thr (4 warps). CTA tile 128x128, warp tile 64x64.
__global__ __launch_bounds__(128) void conv1_wmma() {
    extern __shared__ __nv_bfloat16 sm[];
    const int t = threadIdx.x;
    const int warp = t >> 5;
    const int nbase = blockIdx.x * 128;
    const int ks = blockIdx.y;
    const int wm = (warp >> 1) * 64;
    const int wn = (warp & 1) * 64;

    wmma::fragment<wmma::accumulator, 16, 16, 16, float> acc[4][4];
#pragma unroll
    for (int m = 0; m < 4; ++m)
#pragma unroll
        for (int n = 0; n < 4; ++n) wmma::fill_fragment(acc[m][n], 0.f);

    // per-thread load invariants: idx = i*128 + t, i in 0..7 (1024 16B rows-of-8)
    // mat = i>>1 (0=Ah,1=Al,2=Bh,3=Bl), row = (idx>>1)&127, half = idx&1
    int b_b[8], b_oy[8], b_ox[8]; bool b_v[8];
    int l_mat[8], l_row[8], l_half[8];
#pragma unroll
    for (int i = 0; i < 8; ++i) {
        int idx = i * 128 + t;
        l_mat[i] = idx >> 8; l_row[i] = (idx >> 1) & 127; l_half[i] = idx & 1;
        int px = nbase + l_row[i];
        bool v = px < GN;
        int pc = v ? px : 0;
        int bb = pc / 196, pp = pc - bb * 196;
        b_b[i] = bb; b_oy[i] = pp / 14; b_ox[i] = pp - 14 * (pp / 14); b_v[i] = v;
    }

    uint4 rg[8];
    auto fetch = [&](int ch) {
        const int g = ks * NCH1 + ch;
        const int t9 = g >> 7;
        const int icb = (g & 127) << 4;
        const int ky = t9 / 3, kx = t9 - 3 * (t9 / 3);
#pragma unroll
        for (int i = 0; i < 8; ++i) {
            if (l_mat[i] < 2) {
                const __nv_bfloat16* srcA = (l_mat[i] ? g_wAl : g_wAh) +
                    ((l_row[i] * 9 + t9) << 11) + icb + l_half[i] * 8;
                rg[i] = *(const uint4*)srcA;
            } else {
                int iy = b_oy[i] + ky - 1, ix = b_ox[i] + kx - 1;
                bool inb = b_v[i] && ((unsigned)iy < 14u) && ((unsigned)ix < 14u);
                if (inb) {
                    const __nv_bfloat16* srcB = ((l_mat[i] & 1) ? g_rTl : g_rTh) +
                        ((b_b[i] * 196 + iy * 14 + ix) << 11) + icb + l_half[i] * 8;
                    rg[i] = *(const uint4*)srcB;
                } else {
                    rg[i] = make_uint4(0, 0, 0, 0);
                }
            }
        }
    };
    auto store = [&](int buf) {
        __nv_bfloat16* bp = sm + buf * BUFS;
#pragma unroll
        for (int i = 0; i < 8; ++i)
            *(uint4*)(bp + l_mat[i] * 3072 + l_row[i] * 24 + l_half[i] * 8) = rg[i];
    };

    fetch(0);
    store(0);
    __syncthreads();

    for (int ch = 0; ch < NCH1; ++ch) {
        const int cur = ch & 1;
        const bool more = (ch + 1 < NCH1);
        if (more) fetch(ch + 1);

        const __nv_bfloat16* bp = sm + cur * BUFS;
#pragma unroll
        for (int c = 0; c < 3; ++c) {
            const __nv_bfloat16* Ab = bp + (c == 2 ? AL_O : AH_O);
            const __nv_bfloat16* Bb = bp + (c == 1 ? BL_O : BH_O);
            wmma::fragment<wmma::matrix_b, 16, 16, 16, __nv_bfloat16, wmma::col_major> fb[4];
#pragma unroll
            for (int n = 0; n < 4; ++n)
                wmma::load_matrix_sync(fb[n], Bb + (wn + n * 16) * 24, 24);
#pragma unroll
            for (int m = 0; m < 4; ++m) {
                wmma::fragment<wmma::matrix_a, 16, 16, 16, __nv_bfloat16, wmma::row_major> fa;
                wmma::load_matrix_sync(fa, Ab + (wm + m * 16) * 24, 24);
#pragma unroll
                for (int n = 0; n < 4; ++n)
                    wmma::mma_sync(acc[m][n], fa, fb[n], acc[m][n]);
            }
        }

        if (more) store(cur ^ 1);
        __syncthreads();
    }

    float* base = &g_part[ks][0][0];
#pragma unroll
    for (int m = 0; m < 4; ++m)
#pragma unroll
        for (int n = 0; n < 4; ++n)
            wmma::store_matrix_sync(base + (size_t)(wm + m * 16) * GNP + nbase + wn + n * 16,
                                    acc[m][n], GNP, wmma::mem_row_major);
}

// sum K-split partials + bias + relu -> g_d1 (float4 loads)
__global__ void reduce_relu_kernel(const float* __restrict__ bd1) {
    int i = blockIdx.x * 256 + threadIdx.x;
    if (i >= 128 * (GN / 4)) return;
    int oc = i / (GN / 4);
    int n0 = (i - oc * (GN / 4)) * 4;
    float4 s = make_float4(0.f, 0.f, 0.f, 0.f);
#pragma unroll
    for (int ks = 0; ks < KS1; ++ks) {
        float4 v = *(const float4*)&g_part[ks][oc][n0];
        s.x += v.x; s.y += v.y; s.z += v.z; s.w += v.w;
    }
    float bias = bd1[oc];
    float vals[4] = {s.x + bias, s.y + bias, s.z + bias, s.w + bias};
#pragma unroll
    for (int j = 0; j < 4; ++j) {
        int n = n0 + j;
        int b = n / 196, p = n - b * 196;
        g_d1[b][oc][p] = fmaxf(vals[j], 0.f);
    }
}

// ---------------- conv2 ----------------
__global__ __launch_bounds__(392) void conv2_part(const float* __restrict__ wd2) {
    __shared__ float ds[8][196];
    __shared__ float ws[8][128][9];
    const int b = blockIdx.x, sp = blockIdx.y;
    const int t = threadIdx.x;
    for (int i = t; i < 8 * 196; i += 392) {
        int ic = i / 196, p = i - ic * 196;
        ds[ic][p] = g_d1[b][sp * 8 + ic][p];
    }
    for (int i = t; i < 8 * 128 * 9; i += 392) {
        int ic = i / (128 * 9);
        int r = i - ic * (128 * 9);
        int oc = r / 9, k = r - oc * 9;
        ws[ic][oc][k] = wd2[(size_t)oc * 1152 + (sp * 8 + ic) * 9 + k];
    }
    __syncthreads();
    const int p = t % 49;
    const int g = t / 49;
    const int oy = p / 7, ox = p - 7 * (p / 7);
    float acc[16];
#pragma unroll
    for (int r = 0; r < 16; ++r) acc[r] = 0.f;
    for (int ic = 0; ic < 8; ++ic) {
        float d[9];
#pragma unroll
        for (int ky = 0; ky < 3; ++ky)
#pragma unroll
            for (int kx = 0; kx < 3; ++kx) {
                int iy = 2 * oy - 1 + ky, ix = 2 * ox - 1 + kx;
                bool inb = ((unsigned)iy < 14u) && ((unsigned)ix < 14u);
                d[ky * 3 + kx] = inb ? ds[ic][iy * 14 + ix] : 0.f;
            }
#pragma unroll
        for (int r = 0; r < 16; ++r) {
            const float* w = &ws[ic][g * 16 + r][0];
            float a = acc[r];
#pragma unroll
            for (int k = 0; k < 9; ++k) a += w[k] * d[k];
            acc[r] = a;
        }
    }
#pragma unroll
    for (int r = 0; r < 16; ++r) g_p2[sp][b][g * 16 + r][p] = acc[r];
}

__global__ void conv2_reduce(const float* __restrict__ bd2) {
    int i = blockIdx.x * 256 + threadIdx.x;
    if (i >= BATCH * 128 * 49) return;
    int b = i / (128 * 49);
    int r = i - b * (128 * 49);
    int oc = r / 49, p = r - oc * 49;
    float s = bd2[oc];
#pragma unroll
    for (int sp = 0; sp < C2S; ++sp) s += g_p2[sp][b][oc][p];
    g_d2[b][oc][p] = fmaxf(s, 0.f);
}

// ---------------- conv3 ----------------
__global__ __launch_bounds__(128) void conv3_part(const float* __restrict__ wd3) {
    __shared__ float ds[8][49];
    __shared__ float ws[8][128][9];
    const int b = blockIdx.x, sp = blockIdx.y;
    const int t = threadIdx.x;
    for (int i = t; i < 8 * 49; i += 128) {
        int ic = i / 49, p = i - ic * 49;
        ds[ic][p] = g_d2[b][sp * 8 + ic][p];
    }
    for (int i = t; i < 8 * 128 * 9; i += 128) {
        int ic = i / (128 * 9);
        int r = i - ic * (128 * 9);
        int oc = r / 9, k = r - oc * 9;
        ws[ic][oc][k] = wd3[(size_t)oc * 1152 + (sp * 8 + ic) * 9 + k];
    }
    __syncthreads();
    const int p = t & 15;
    const int g = t >> 4;
    const int oy = p >> 2, ox = p & 3;
    float acc[16];
#pragma unroll
    for (int r = 0; r < 16; ++r) acc[r] = 0.f;
    for (int ic = 0; ic < 8; ++ic) {
        float d[9];
#pragma unroll
        for (int ky = 0; ky < 3; ++ky)
#pragma unroll
            for (int kx = 0; kx < 3; ++kx) {
                int iy = 2 * oy - 1 + ky, ix = 2 * ox - 1 + kx;
                bool inb = ((unsigned)iy < 7u) && ((unsigned)ix < 7u);
                d[ky * 3 + kx] = inb ? ds[ic][iy * 7 + ix] : 0.f;
            }
#pragma unroll
        for (int r = 0; r < 16; ++r) {
            const float* w = &ws[ic][g * 16 + r][0];
            float a = acc[r];
#pragma unroll
            for (int k = 0; k < 9; ++k) a += w[k] * d[k];
            acc[r] = a;
        }
    }
#pragma unroll
    for (int r = 0; r < 16; ++r) g_p3[sp][b][g * 16 + r][p] = acc[r];
}

__global__ void conv3_reduce(const float* __restrict__ bd3) {
    int i = blockIdx.x * 256 + threadIdx.x;
    if (i >= BATCH * 128 * 16) return;
    int b = i / (128 * 16);
    int r = i - b * (128 * 16);
    int oc = r / 16, p = r & 15;
    float s = bd3[oc];
#pragma unroll
    for (int sp = 0; sp < C3S; ++sp) s += g_p3[sp][b][oc][p];
    g_d3[b][oc][p] = fmaxf(s, 0.f);
}

// ---------------- heads ----------------
__global__ void heads_kernel(const float* __restrict__ wt1, const float* __restrict__ bt1,
                             const float* __restrict__ wt2, const float* __restrict__ bt2,
                             const float* __restrict__ wt3, const float* __restrict__ bt3) {
    int b = blockIdx.x;
    int a = blockIdx.y * 256 + threadIdx.x;
    if (a >= NA) return;
    float acc;
    if (a < 1176) {
        int c = a / 196, p = a - c * 196;
        acc = bt1[c];
        const float* w = wt1 + c * 128;
        for (int ic = 0; ic < 128; ++ic) acc += g_d1[b][ic][p] * w[ic];
    } else if (a < 1470) {
        int a2 = a - 1176;
        int c = a2 / 49, p = a2 - c * 49;
        acc = bt2[c];
        const float* w = wt2 + c * 128;
        for (int ic = 0; ic < 128; ++ic) acc += g_d2[b][ic][p] * w[ic];
    } else {
        int a3 = a - 1470;
        int c = a3 / 16, p = a3 & 15;
        acc = bt3[c];
        const float* w = wt3 + c * 128;
        for (int ic = 0; ic < 128; ++ic) acc += g_d3[b][ic][p] * w[ic];
    }
    g_scores[b][a] = acc;
}

// ---------------- NMS + top-6 ----------------
__global__ __launch_bounds__(1024) void nms_topk_kernel(const float* __restrict__ anchors,
                                                        float* __restrict__ out) {
    __shared__ unsigned long long key[2048];
    const int b = blockIdx.x;
    const int tid = threadIdx.x;

    for (int a = tid; a < 2048; a += 1024) {
        unsigned long long k = 0ull;
        if (a < NA) {
            unsigned u = __float_as_uint(g_scores[b][a]);
            unsigned us = (u & 0x80000000u) ? ~u : (u | 0x80000000u);
            k = ((unsigned long long)us << 32) | (unsigned)(~(unsigned)a);
        }
        key[a] = k;
    }
    for (int kk = 2; kk <= 2048; kk <<= 1) {
        for (int j = kk >> 1; j > 0; j >>= 1) {
            __syncthreads();
            for (int i = tid; i < 2048; i += 1024) {
                int ixj = i ^ j;
                if (ixj > i) {
                    unsigned long long x = key[i], y = key[ixj];
                    bool desc = ((i & kk) == 0);
                    if (desc ? (x < y) : (x > y)) { key[i] = y; key[ixj] = x; }
                }
            }
        }
    }
    __syncthreads();

    if (tid == 0) {
        float ky0[TOPN], kx0[TOPN], ky1[TOPN], kx1[TOPN], karea[TOPN], kprob[TOPN];
        int kidx[TOPN];
        int nk = 0;
        for (int r = 0; r < NA && nk < TOPN; ++r) {
            unsigned long long k = key[r];
            int idx = (int)(~(unsigned)k);
            if (idx >= NA) break;
            float y0 = anchors[idx * 4 + 0], x0 = anchors[idx * 4 + 1];
            float y1 = anchors[idx * 4 + 2], x1 = anchors[idx * 4 + 3];
            float area = (y1 - y0) * (x1 - x0);
            bool sup = false;
            for (int s = 0; s < nk; ++s) {
                float ih = fminf(y1, ky1[s]) - fmaxf(y0, ky0[s]); if (ih < 0.f) ih = 0.f;
                float iw = fminf(x1, kx1[s]) - fmaxf(x0, kx0[s]); if (iw < 0.f) iw = 0.f;
                float inter = ih * iw;
                if (inter > 0.25f * (area + karea[s] - inter)) { sup = true; break; }
            }
            if (!sup) {
                unsigned us = (unsigned)(k >> 32);
                unsigned u = (us & 0x80000000u) ? (us ^ 0x80000000u) : ~us;
                ky0[nk] = y0; kx0[nk] = x0; ky1[nk] = y1; kx1[nk] = x1;
                karea[nk] = area; kidx[nk] = idx; kprob[nk] = __uint_as_float(u);
                ++nk;
            }
        }
        int fi = 0;
        while (nk < TOPN) {
            bool used = false;
            for (int s = 0; s < nk; ++s) if (kidx[s] == fi) used = true;
            if (!used) {
                ky0[nk] = anchors[fi * 4 + 0]; kx0[nk] = anchors[fi * 4 + 1];
                ky1[nk] = anchors[fi * 4 + 2]; kx1[nk] = anchors[fi * 4 + 3];
                karea[nk] = 0.f; kidx[nk] = fi; kprob[nk] = -INFINITY;
                ++nk;
            }
            ++fi;
        }
        for (int s = 0; s < TOPN; ++s) {
            int o = b * TOPN + s;
            g_boxes[b][s][0] = (int)kx0[s];
            g_boxes[b][s][1] = (int)ky0[s];
            g_boxes[b][s][2] = (int)kx1[s];
            g_boxes[b][s][3] = (int)ky1[s];
            out[OFF_COORDS + o * 4 + 0] = kx0[s];
            out[OFF_COORDS + o * 4 + 1] = ky0[s];
            out[OFF_COORDS + o * 4 + 2] = kx1[s];
            out[OFF_COORDS + o * 4 + 3] = ky1[s];
            out[OFF_PROB + o] = kprob[s];
            out[OFF_IDX + o] = (float)kidx[s];
        }
    }
}

// ---------------- crop-resize: 4 rows/block, float4 stores ----------------
// grid (56 row-groups, 3 ch, 48 boxes), 224 threads: t%56 -> x quad, t/56 -> row in group
__global__ __launch_bounds__(224) void crop_kernel(const float* __restrict__ xin,
                                                   float* __restrict__ out) {
    const int t  = threadIdx.x;
    const int xq = (t % 56) * 4;
    const int oy = blockIdx.x * 4 + t / 56;
    const int c  = blockIdx.y;
    const int bs = blockIdx.z;
    const int b  = bs / TOPN;
    const int s  = bs - b * TOPN;

    const int X0 = g_boxes[b][s][0], Y0 = g_boxes[b][s][1];
    const int X1 = g_boxes[b][s][2], Y1 = g_boxes[b][s][3];

    float ty = __fdiv_rn((float)oy, 223.0f);
    float sy = __fadd_rn((float)Y0, __fmul_rn(ty, (float)(Y1 - 1 - Y0)));
    int y0i = (int)floorf(sy);
    int y1i = min(y0i + 1, Y1 - 1);
    float wy = __fadd_rn(sy, -(float)y0i);

    const float* img = xin + ((size_t)b * 3 + c) * 448 * 448;
    auto fetch = [&](int y, int x) -> float {
        y -= 224; x -= 224;
        if ((unsigned)y < 448u && (unsigned)x < 448u) return img[y * 448 + x];
        return 0.f;
    };

    float4 res;
    float* rp = &res.x;
#pragma unroll
    for (int j = 0; j < 4; ++j) {
        int ox = xq + j;
        float tx = __fdiv_rn((float)ox, 223.0f);
        float sx = __fadd_rn((float)X0, __fmul_rn(tx, (float)(X1 - 1 - X0)));
        int x0i = (int)floorf(sx);
        int x1i = min(x0i + 1, X1 - 1);
        float wx = __fadd_rn(sx, -(float)x0i);

        float f00 = fetch(y0i, x0i), f01 = fetch(y0i, x1i);
        float f10 = fetch(y1i, x0i), f11 = fetch(y1i, x1i);
        float top = (1.f - wx) * f00 + wx * f01;
        float bot = (1.f - wx) * f10 + wx * f11;
        rp[j] = (1.f - wy) * top + wy * bot;
    }
    *(float4*)&out[(((size_t)bs * 3 + c) * OUTP + oy) * OUTP + xq] = res;
}

// ---------------- launch ----------------
extern "C" void kernel_launch(void* const* d_in, const int* in_sizes, int n_in,
                              void* d_out, int out_size) {
    const float* x       = (const float*)d_in[0];
    const float* rpn     = (const float*)d_in[1];
    const float* anchors = (const float*)d_in[2];
    const float* wd1 = (const float*)d_in[3];
    const float* bd1 = (const float*)d_in[4];
    const float* wd2 = (const float*)d_in[5];
    const float* bd2 = (const float*)d_in[6];
    const float* wd3 = (const float*)d_in[7];
    const float* bd3 = (const float*)d_in[8];
    const float* wt1 = (const float*)d_in[9];
    const float* bt1 = (const float*)d_in[10];
    const float* wt2 = (const float*)d_in[11];
    const float* bt2 = (const float*)d_in[12];
    const float* wt3 = (const float*)d_in[13];
    const float* bt3 = (const float*)d_in[14];
    float* out = (float*)d_out;

    prep_all<<<1536, 256>>>(wd1, rpn);
    conv1_wmma<<<dim3(13, KS1), 128, DYNSMEM>>>();
    reduce_relu_kernel<<<(128 * (GN / 4) + 255) / 256, 256>>>(bd1);
    conv2_part<<<dim3(BATCH, C2S), 392>>>(wd2);
    conv2_reduce<<<(BATCH * 128 * 49 + 255) / 256, 256>>>(bd2);
    conv3_part<<<dim3(BATCH, C3S), 128>>>(wd3);
    conv3_reduce<<<(BATCH * 128 * 16 + 255) / 256, 256>>>(bd3);
    heads_kernel<<<dim3(BATCH, 7), 256>>>(wt1, bt1, wt2, bt2, wt3, bt3);
    nms_topk_kernel<<<BATCH, 1024>>>(anchors, out);
    crop_kernel<<<dim3(56, 3, BATCH * TOPN), 224>>>(x, out);
}

// round 8
// speedup vs baseline: 1.1805x; 1.1805x over previous
#include <cuda_runtime.h>
#include <cuda_bf16.h>
#include <mma.h>
#include <math.h>
#include <stdint.h>

using namespace nvcuda;

// ---------------- problem constants ----------------
#define BATCH 8
#define NA    1614
#define TOPN  6
#define OUTP  224
#define GN    1568              // 8*196 px
#define GNP   1664              // padded N (13 tiles * 128)
#define GK    18432             // 2048*9
#define KS1   32                // conv1 K-splits
#define NCH1  36                // chunks of k=16 per split (18432/32/16)
#define C2S   16
#define C3S   16

#define OFF_COORDS 7225344
#define OFF_PROB   7225536
#define OFF_IDX    7225584

// smem element offsets (bf16 elems), ldm 24 (16 used + 8 pad)
#define AH_O  0
#define AL_O  3072
#define BH_O  6144
#define BL_O  9216
#define BUFS  12288
#define DYNSMEM (2 * BUFS * 2)      // 49152 bytes

// ---------------- scratch globals ----------------
__device__ __nv_bfloat16 g_wAh[128 * 9 * 2048];   // weights [oc][t9][ic] hi
__device__ __nv_bfloat16 g_wAl[128 * 9 * 2048];   // lo
__device__ __nv_bfloat16 g_rTh[8 * 196 * 2048];   // rpn NHWC [b][p][ic] hi
__device__ __nv_bfloat16 g_rTl[8 * 196 * 2048];   // lo
__device__ float g_part[KS1][128][GNP];
__device__ float g_d1[BATCH][128][196];
__device__ float g_d2[BATCH][128][49];
__device__ float g_d3[BATCH][128][16];
__device__ float g_p2[C2S][BATCH][128][49];
__device__ float g_p3[C3S][BATCH][128][16];
__device__ float g_scores[BATCH][NA];
__device__ int   g_boxes[BATCH][TOPN][4];

// ---------------- merged prep: blocks [0,1024) = weights, [1024,1536) = rpn ----------------
__global__ __launch_bounds__(256) void prep_all(const float* __restrict__ wd1,
                                                const float* __restrict__ rpn) {
    if (blockIdx.x < 1024) {
        __shared__ float w[2304];
        const int oc = blockIdx.x >> 3;
        const int ic0 = (blockIdx.x & 7) * 256;
        const float* src = wd1 + (size_t)oc * GK + (size_t)ic0 * 9;
        for (int i = threadIdx.x; i < 2304; i += 256) w[i] = src[i];
        __syncthreads();
        for (int i = threadIdx.x; i < 2304; i += 256) {
            int t9 = i >> 8, ic = i & 255;
            float a = w[ic * 9 + t9];
            __nv_bfloat16 hi = __float2bfloat16(a);
            __nv_bfloat16 lo = __float2bfloat16(a - __bfloat162float(hi));
            int o = (oc * 9 + t9) * 2048 + ic0 + ic;
            g_wAh[o] = hi; g_wAl[o] = lo;
        }
    } else {
        __shared__ float sm_[32][197];
        const int r = blockIdx.x - 1024;
        const int b = r >> 6;
        const int ic0 = (r & 63) * 32;
        const float* src = rpn + ((size_t)b * 2048 + ic0) * 196;
        for (int i = threadIdx.x; i < 32 * 196; i += 256) {
            int ic = i / 196, p = i - ic * 196;
            sm_[ic][p] = src[ic * 196 + p];
        }
        __syncthreads();
        for (int i = threadIdx.x; i < 32 * 196; i += 256) {
            int p = i >> 5, ic = i & 31;
            float a = sm_[ic][p];
            __nv_bfloat16 hi = __float2bfloat16(a);
            __nv_bfloat16 lo = __float2bfloat16(a - __bfloat162float(hi));
            int o = (b * 196 + p) * 2048 + ic0 + ic;
            g_rTh[o] = hi; g_rTl[o] = lo;
        }
    }
}

// ---------------- conv1 via wmma bf16 hi/lo split (R6-proven config) ----------------
// grid (13 n-tiles, 32 k-splits), 256 thr (8 warps). CTA tile 128x128, warp tile 64x32.
__global__ __launch_bounds__(256) void conv1_wmma() {
    extern __shared__ __nv_bfloat16 sm[];
    const int t = threadIdx.x;
    const int warp = t >> 5;
    const int nbase = blockIdx.x * 128;
    const int ks = blockIdx.y;
    const int wm = (warp >> 2) * 64;
    const int wn = (warp & 3) * 32;

    wmma::fragment<wmma::accumulator, 16, 16, 16, float> acc[4][2];
#pragma unroll
    for (int m = 0; m < 4; ++m)
#pragma unroll
        for (int n = 0; n < 2; ++n) wmma::fill_fragment(acc[m][n], 0.f);

    int b_b[2], b_oy[2], b_ox[2]; bool b_v[2];
    int l_arr[2], l_row[2], l_half[2];
#pragma unroll
    for (int i = 0; i < 2; ++i) {
        int idx = i * 256 + t;
        l_arr[i] = idx >> 8; l_row[i] = (idx >> 1) & 127; l_half[i] = idx & 1;
        int px = nbase + l_row[i];
        bool v = px < GN;
        int pc = v ? px : 0;
        int bb = pc / 196, pp = pc - bb * 196;
        b_b[i] = bb; b_oy[i] = pp / 14; b_ox[i] = pp - 14 * (pp / 14); b_v[i] = v;
    }

    uint4 ra[2], rb[2];
    auto fetch = [&](int ch) {
        const int g = ks * NCH1 + ch;
        const int t9 = g >> 7;
        const int icb = (g & 127) << 4;
        const int ky = t9 / 3, kx = t9 - 3 * (t9 / 3);
#pragma unroll
        for (int i = 0; i < 2; ++i) {
            const __nv_bfloat16* srcA = (l_arr[i] ? g_wAl : g_wAh) +
                ((l_row[i] * 9 + t9) << 11) + icb + l_half[i] * 8;
            ra[i] = *(const uint4*)srcA;
            int iy = b_oy[i] + ky - 1, ix = b_ox[i] + kx - 1;
            bool inb = b_v[i] && ((unsigned)iy < 14u) && ((unsigned)ix < 14u);
            if (inb) {
                const __nv_bfloat16* srcB = (l_arr[i] ? g_rTl : g_rTh) +
                    ((b_b[i] * 196 + iy * 14 + ix) << 11) + icb + l_half[i] * 8;
                rb[i] = *(const uint4*)srcB;
            } else {
                rb[i] = make_uint4(0, 0, 0, 0);
            }
        }
    };
    auto store = [&](int buf) {
        __nv_bfloat16* bp = sm + buf * BUFS;
#pragma unroll
        for (int i = 0; i < 2; ++i) {
            *(uint4*)(bp + (l_arr[i] ? AL_O : AH_O) + l_row[i] * 24 + l_half[i] * 8) = ra[i];
            *(uint4*)(bp + (l_arr[i] ? BL_O : BH_O) + l_row[i] * 24 + l_half[i] * 8) = rb[i];
        }
    };

    fetch(0);
    store(0);
    __syncthreads();

    for (int ch = 0; ch < NCH1; ++ch) {
        const int cur = ch & 1;
        const bool more = (ch + 1 < NCH1);
        if (more) fetch(ch + 1);

        const __nv_bfloat16* bp = sm + cur * BUFS;
#pragma unroll
        for (int c = 0; c < 3; ++c) {
            const __nv_bfloat16* Ab = bp + (c == 2 ? AL_O : AH_O);
            const __nv_bfloat16* Bb = bp + (c == 1 ? BL_O : BH_O);
            wmma::fragment<wmma::matrix_b, 16, 16, 16, __nv_bfloat16, wmma::col_major> fb[2];
#pragma unroll
            for (int n = 0; n < 2; ++n)
                wmma::load_matrix_sync(fb[n], Bb + (wn + n * 16) * 24, 24);
#pragma unroll
            for (int m = 0; m < 4; ++m) {
                wmma::fragment<wmma::matrix_a, 16, 16, 16, __nv_bfloat16, wmma::row_major> fa;
                wmma::load_matrix_sync(fa, Ab + (wm + m * 16) * 24, 24);
                wmma::mma_sync(acc[m][0], fa, fb[0], acc[m][0]);
                wmma::mma_sync(acc[m][1], fa, fb[1], acc[m][1]);
            }
        }

        if (more) store(cur ^ 1);
        __syncthreads();
    }

    float* base = &g_part[ks][0][0];
#pragma unroll
    for (int m = 0; m < 4; ++m)
#pragma unroll
        for (int n = 0; n < 2; ++n)
            wmma::store_matrix_sync(base + (size_t)(wm + m * 16) * GNP + nbase + wn + n * 16,
                                    acc[m][n], GNP, wmma::mem_row_major);
}

// sum K-split partials + bias + relu -> g_d1 (float4 loads)
__global__ void reduce_relu_kernel(const float* __restrict__ bd1) {
    int i = blockIdx.x * 256 + threadIdx.x;
    if (i >= 128 * (GN / 4)) return;
    int oc = i / (GN / 4);
    int n0 = (i - oc * (GN / 4)) * 4;
    float4 s = make_float4(0.f, 0.f, 0.f, 0.f);
#pragma unroll
    for (int ks = 0; ks < KS1; ++ks) {
        float4 v = *(const float4*)&g_part[ks][oc][n0];
        s.x += v.x; s.y += v.y; s.z += v.z; s.w += v.w;
    }
    float bias = bd1[oc];
    float vals[4] = {s.x + bias, s.y + bias, s.z + bias, s.w + bias};
#pragma unroll
    for (int j = 0; j < 4; ++j) {
        int n = n0 + j;
        int b = n / 196, p = n - b * 196;
        g_d1[b][oc][p] = fmaxf(vals[j], 0.f);
    }
}

// ---------------- conv2: grid (8 b, 16 ic-splits, 2 oc-groups), 392 thr ----------------
__global__ __launch_bounds__(392) void conv2_part(const float* __restrict__ wd2) {
    __shared__ float ds[8][196];
    __shared__ float ws[8][64][9];
    const int b = blockIdx.x, sp = blockIdx.y, ocg = blockIdx.z;
    const int t = threadIdx.x;
    for (int i = t; i < 8 * 196; i += 392) {
        int ic = i / 196, p = i - ic * 196;
        ds[ic][p] = g_d1[b][sp * 8 + ic][p];
    }
    for (int i = t; i < 8 * 64 * 9; i += 392) {
        int ic = i / (64 * 9);
        int r = i - ic * (64 * 9);
        int oc = r / 9, k = r - oc * 9;
        ws[ic][oc][k] = wd2[(size_t)(ocg * 64 + oc) * 1152 + (sp * 8 + ic) * 9 + k];
    }
    __syncthreads();
    const int p = t % 49;
    const int g = t / 49;          // 0..7 -> 8 oc each
    const int oy = p / 7, ox = p - 7 * (p / 7);
    float acc[8];
#pragma unroll
    for (int r = 0; r < 8; ++r) acc[r] = 0.f;
    for (int ic = 0; ic < 8; ++ic) {
        float d[9];
#pragma unroll
        for (int ky = 0; ky < 3; ++ky)
#pragma unroll
            for (int kx = 0; kx < 3; ++kx) {
                int iy = 2 * oy - 1 + ky, ix = 2 * ox - 1 + kx;
                bool inb = ((unsigned)iy < 14u) && ((unsigned)ix < 14u);
                d[ky * 3 + kx] = inb ? ds[ic][iy * 14 + ix] : 0.f;
            }
#pragma unroll
        for (int r = 0; r < 8; ++r) {
            const float* w = &ws[ic][g * 8 + r][0];
            float a = acc[r];
#pragma unroll
            for (int k = 0; k < 9; ++k) a += w[k] * d[k];
            acc[r] = a;
        }
    }
#pragma unroll
    for (int r = 0; r < 8; ++r) g_p2[sp][b][ocg * 64 + g * 8 + r][p] = acc[r];
}

__global__ void conv2_reduce(const float* __restrict__ bd2) {
    int i = blockIdx.x * 256 + threadIdx.x;
    if (i >= BATCH * 128 * 49) return;
    int b = i / (128 * 49);
    int r = i - b * (128 * 49);
    int oc = r / 49, p = r - oc * 49;
    float s = bd2[oc];
#pragma unroll
    for (int sp = 0; sp < C2S; ++sp) s += g_p2[sp][b][oc][p];
    g_d2[b][oc][p] = fmaxf(s, 0.f);
}

// ---------------- conv3: grid (8 b, 16 ic-splits, 2 oc-groups), 128 thr ----------------
__global__ __launch_bounds__(128) void conv3_part(const float* __restrict__ wd3) {
    __shared__ float ds[8][49];
    __shared__ float ws[8][64][9];
    const int b = blockIdx.x, sp = blockIdx.y, ocg = blockIdx.z;
    const int t = threadIdx.x;
    for (int i = t; i < 8 * 49; i += 128) {
        int ic = i / 49, p = i - ic * 49;
        ds[ic][p] = g_d2[b][sp * 8 + ic][p];
    }
    for (int i = t; i < 8 * 64 * 9; i += 128) {
        int ic = i / (64 * 9);
        int r = i - ic * (64 * 9);
        int oc = r / 9, k = r - oc * 9;
        ws[ic][oc][k] = wd3[(size_t)(ocg * 64 + oc) * 1152 + (sp * 8 + ic) * 9 + k];
    }
    __syncthreads();
    const int p = t & 15;
    const int g = t >> 4;          // 0..7 -> 8 oc each
    const int oy = p >> 2, ox = p & 3;
    float acc[8];
#pragma unroll
    for (int r = 0; r < 8; ++r) acc[r] = 0.f;
    for (int ic = 0; ic < 8; ++ic) {
        float d[9];
#pragma unroll
        for (int ky = 0; ky < 3; ++ky)
#pragma unroll
            for (int kx = 0; kx < 3; ++kx) {
                int iy = 2 * oy - 1 + ky, ix = 2 * ox - 1 + kx;
                bool inb = ((unsigned)iy < 7u) && ((unsigned)ix < 7u);
                d[ky * 3 + kx] = inb ? ds[ic][iy * 7 + ix] : 0.f;
            }
#pragma unroll
        for (int r = 0; r < 8; ++r) {
            const float* w = &ws[ic][g * 8 + r][0];
            float a = acc[r];
#pragma unroll
            for (int k = 0; k < 9; ++k) a += w[k] * d[k];
            acc[r] = a;
        }
    }
#pragma unroll
    for (int r = 0; r < 8; ++r) g_p3[sp][b][ocg * 64 + g * 8 + r][p] = acc[r];
}

__global__ void conv3_reduce(const float* __restrict__ bd3) {
    int i = blockIdx.x * 256 + threadIdx.x;
    if (i >= BATCH * 128 * 16) return;
    int b = i / (128 * 16);
    int r = i - b * (128 * 16);
    int oc = r / 16, p = r & 15;
    float s = bd3[oc];
#pragma unroll
    for (int sp = 0; sp < C3S; ++sp) s += g_p3[sp][b][oc][p];
    g_d3[b][oc][p] = fmaxf(s, 0.f);
}

// ---------------- heads ----------------
__global__ void heads_kernel(const float* __restrict__ wt1, const float* __restrict__ bt1,
                             const float* __restrict__ wt2, const float* __restrict__ bt2,
                             const float* __restrict__ wt3, const float* __restrict__ bt3) {
    int b = blockIdx.x;
    int a = blockIdx.y * 256 + threadIdx.x;
    if (a >= NA) return;
    float acc;
    if (a < 1176) {
        int c = a / 196, p = a - c * 196;
        acc = bt1[c];
        const float* w = wt1 + c * 128;
        for (int ic = 0; ic < 128; ++ic) acc += g_d1[b][ic][p] * w[ic];
    } else if (a < 1470) {
        int a2 = a - 1176;
        int c = a2 / 49, p = a2 - c * 49;
        acc = bt2[c];
        const float* w = wt2 + c * 128;
        for (int ic = 0; ic < 128; ++ic) acc += g_d2[b][ic][p] * w[ic];
    } else {
        int a3 = a - 1470;
        int c = a3 / 16, p = a3 & 15;
        acc = bt3[c];
        const float* w = wt3 + c * 128;
        for (int ic = 0; ic < 128; ++ic) acc += g_d3[b][ic][p] * w[ic];
    }
    g_scores[b][a] = acc;
}

// ---------------- NMS + top-6 ----------------
__global__ __launch_bounds__(1024) void nms_topk_kernel(const float* __restrict__ anchors,
                                                        float* __restrict__ out) {
    __shared__ unsigned long long key[2048];
    const int b = blockIdx.x;
    const int tid = threadIdx.x;

    for (int a = tid; a < 2048; a += 1024) {
        unsigned long long k = 0ull;
        if (a < NA) {
            unsigned u = __float_as_uint(g_scores[b][a]);
            unsigned us = (u & 0x80000000u) ? ~u : (u | 0x80000000u);
            k = ((unsigned long long)us << 32) | (unsigned)(~(unsigned)a);
        }
        key[a] = k;
    }
    for (int kk = 2; kk <= 2048; kk <<= 1) {
        for (int j = kk >> 1; j > 0; j >>= 1) {
            __syncthreads();
            for (int i = tid; i < 2048; i += 1024) {
                int ixj = i ^ j;
                if (ixj > i) {
                    unsigned long long x = key[i], y = key[ixj];
                    bool desc = ((i & kk) == 0);
                    if (desc ? (x < y) : (x > y)) { key[i] = y; key[ixj] = x; }
                }
            }
        }
    }
    __syncthreads();

    if (tid == 0) {
        float ky0[TOPN], kx0[TOPN], ky1[TOPN], kx1[TOPN], karea[TOPN], kprob[TOPN];
        int kidx[TOPN];
        int nk = 0;
        for (int r = 0; r < NA && nk < TOPN; ++r) {
            unsigned long long k = key[r];
            int idx = (int)(~(unsigned)k);
            if (idx >= NA) break;
            float y0 = anchors[idx * 4 + 0], x0 = anchors[idx * 4 + 1];
            float y1 = anchors[idx * 4 + 2], x1 = anchors[idx * 4 + 3];
            float area = (y1 - y0) * (x1 - x0);
            bool sup = false;
            for (int s = 0; s < nk; ++s) {
                float ih = fminf(y1, ky1[s]) - fmaxf(y0, ky0[s]); if (ih < 0.f) ih = 0.f;
                float iw = fminf(x1, kx1[s]) - fmaxf(x0, kx0[s]); if (iw < 0.f) iw = 0.f;
                float inter = ih * iw;
                if (inter > 0.25f * (area + karea[s] - inter)) { sup = true; break; }
            }
            if (!sup) {
                unsigned us = (unsigned)(k >> 32);
                unsigned u = (us & 0x80000000u) ? (us ^ 0x80000000u) : ~us;
                ky0[nk] = y0; kx0[nk] = x0; ky1[nk] = y1; kx1[nk] = x1;
                karea[nk] = area; kidx[nk] = idx; kprob[nk] = __uint_as_float(u);
                ++nk;
            }
        }
        int fi = 0;
        while (nk < TOPN) {
            bool used = false;
            for (int s = 0; s < nk; ++s) if (kidx[s] == fi) used = true;
            if (!used) {
                ky0[nk] = anchors[fi * 4 + 0]; kx0[nk] = anchors[fi * 4 + 1];
                ky1[nk] = anchors[fi * 4 + 2]; kx1[nk] = anchors[fi * 4 + 3];
                karea[nk] = 0.f; kidx[nk] = fi; kprob[nk] = -INFINITY;
                ++nk;
            }
            ++fi;
        }
        for (int s = 0; s < TOPN; ++s) {
            int o = b * TOPN + s;
            g_boxes[b][s][0] = (int)kx0[s];
            g_boxes[b][s][1] = (int)ky0[s];
            g_boxes[b][s][2] = (int)kx1[s];
            g_boxes[b][s][3] = (int)ky1[s];
            out[OFF_COORDS + o * 4 + 0] = kx0[s];
            out[OFF_COORDS + o * 4 + 1] = ky0[s];
            out[OFF_COORDS + o * 4 + 2] = kx1[s];
            out[OFF_COORDS + o * 4 + 3] = ky1[s];
            out[OFF_PROB + o] = kprob[s];
            out[OFF_IDX + o] = (float)kidx[s];
        }
    }
}

// ---------------- crop-resize: 4 rows/block, float4 stores ----------------
__global__ __launch_bounds__(224) void crop_kernel(const float* __restrict__ xin,
                                                   float* __restrict__ out) {
    const int t  = threadIdx.x;
    const int xq = (t % 56) * 4;
    const int oy = blockIdx.x * 4 + t / 56;
    const int c  = blockIdx.y;
    const int bs = blockIdx.z;
    const int b  = bs / TOPN;
    const int s  = bs - b * TOPN;

    const int X0 = g_boxes[b][s][0], Y0 = g_boxes[b][s][1];
    const int X1 = g_boxes[b][s][2], Y1 = g_boxes[b][s][3];

    float ty = __fdiv_rn((float)oy, 223.0f);
    float sy = __fadd_rn((float)Y0, __fmul_rn(ty, (float)(Y1 - 1 - Y0)));
    int y0i = (int)floorf(sy);
    int y1i = min(y0i + 1, Y1 - 1);
    float wy = __fadd_rn(sy, -(float)y0i);

    const float* img = xin + ((size_t)b * 3 + c) * 448 * 448;
    auto fetch = [&](int y, int x) -> float {
        y -= 224; x -= 224;
        if ((unsigned)y < 448u && (unsigned)x < 448u) return img[y * 448 + x];
        return 0.f;
    };

    float4 res;
    float* rp = &res.x;
#pragma unroll
    for (int j = 0; j < 4; ++j) {
        int ox = xq + j;
        float tx = __fdiv_rn((float)ox, 223.0f);
        float sx = __fadd_rn((float)X0, __fmul_rn(tx, (float)(X1 - 1 - X0)));
        int x0i = (int)floorf(sx);
        int x1i = min(x0i + 1, X1 - 1);
        float wx = __fadd_rn(sx, -(float)x0i);

        float f00 = fetch(y0i, x0i), f01 = fetch(y0i, x1i);
        float f10 = fetch(y1i, x0i), f11 = fetch(y1i, x1i);
        float top = (1.f - wx) * f00 + wx * f01;
        float bot = (1.f - wx) * f10 + wx * f11;
        rp[j] = (1.f - wy) * top + wy * bot;
    }
    *(float4*)&out[(((size_t)bs * 3 + c) * OUTP + oy) * OUTP + xq] = res;
}

// ---------------- launch ----------------
extern "C" void kernel_launch(void* const* d_in, const int* in_sizes, int n_in,
                              void* d_out, int out_size) {
    const float* x       = (const float*)d_in[0];
    const float* rpn     = (const float*)d_in[1];
    const float* anchors = (const float*)d_in[2];
    const float* wd1 = (const float*)d_in[3];
    const float* bd1 = (const float*)d_in[4];
    const float* wd2 = (const float*)d_in[5];
    const float* bd2 = (const float*)d_in[6];
    const float* wd3 = (const float*)d_in[7];
    const float* bd3 = (const float*)d_in[8];
    const float* wt1 = (const float*)d_in[9];
    const float* bt1 = (const float*)d_in[10];
    const float* wt2 = (const float*)d_in[11];
    const float* bt2 = (const float*)d_in[12];
    const float* wt3 = (const float*)d_in[13];
    const float* bt3 = (const float*)d_in[14];
    float* out = (float*)d_out;

    prep_all<<<1536, 256>>>(wd1, rpn);
    conv1_wmma<<<dim3(13, KS1), 256, DYNSMEM>>>();
    reduce_relu_kernel<<<(128 * (GN / 4) + 255) / 256, 256>>>(bd1);
    conv2_part<<<dim3(BATCH, C2S, 2), 392>>>(wd2);
    conv2_reduce<<<(BATCH * 128 * 49 + 255) / 256, 256>>>(bd2);
    conv3_part<<<dim3(BATCH, C3S, 2), 128>>>(wd3);
    conv3_reduce<<<(BATCH * 128 * 16 + 255) / 256, 256>>>(bd3);
    heads_kernel<<<dim3(BATCH, 7), 256>>>(wt1, bt1, wt2, bt2, wt3, bt3);
    nms_topk_kernel<<<BATCH, 1024>>>(anchors, out);
    crop_kernel<<<dim3(56, 3, BATCH * TOPN), 224>>>(x, out);
}

// round 9
// speedup vs baseline: 1.2072x; 1.0226x over previous
#include <cuda_runtime.h>
#include <cuda_bf16.h>
#include <mma.h>
#include <math.h>
#include <stdint.h>

using namespace nvcuda;

// ---------------- problem constants ----------------
#define BATCH 8
#define NA    1614
#define TOPN  6
#define OUTP  224
#define GN    1568              // 8*196 px
#define GK    18432             // 2048*9
#define NSLOT 295               // conv1 persistent slots (23*9 + 22*4)
#define C2S   32
#define C3S   32

#define OFF_COORDS 7225344
#define OFF_PROB   7225536
#define OFF_IDX    7225584

// smem element offsets (bf16 elems), ldm 24 (16 used + 8 pad)
#define AH_O  0
#define AL_O  3072
#define BH_O  6144
#define BL_O  9216
#define BUFS  12288
#define DYNSMEM (2 * BUFS * 2)      // 49152 bytes

// ---------------- scratch globals ----------------
__device__ __nv_bfloat16 g_wAh[128 * 9 * 2048];   // weights [oc][t9][ic] hi
__device__ __nv_bfloat16 g_wAl[128 * 9 * 2048];   // lo
__device__ __nv_bfloat16 g_rTh[8 * 196 * 2048];   // rpn NHWC [b][p][ic] hi
__device__ __nv_bfloat16 g_rTl[8 * 196 * 2048];   // lo
__device__ float g_part[NSLOT][128][128];         // per-slot conv1 partials (18.9MB)
__device__ float g_d1[BATCH][128][196];
__device__ float g_d2[BATCH][128][49];
__device__ float g_d3[BATCH][128][16];
__device__ float g_p2[C2S][BATCH][128][49];
__device__ float g_p3[C3S][BATCH][128][16];
__device__ float g_scores[BATCH][NA];
__device__ int   g_boxes[BATCH][TOPN][4];

// ---------------- merged prep: blocks [0,1024) = weights, [1024,1536) = rpn ----------------
__global__ __launch_bounds__(256) void prep_all(const float* __restrict__ wd1,
                                                const float* __restrict__ rpn) {
    if (blockIdx.x < 1024) {
        __shared__ float w[2304];
        const int oc = blockIdx.x >> 3;
        const int ic0 = (blockIdx.x & 7) * 256;
        const float* src = wd1 + (size_t)oc * GK + (size_t)ic0 * 9;
        for (int i = threadIdx.x; i < 2304; i += 256) w[i] = src[i];
        __syncthreads();
        for (int i = threadIdx.x; i < 2304; i += 256) {
            int t9 = i >> 8, ic = i & 255;
            float a = w[ic * 9 + t9];
            __nv_bfloat16 hi = __float2bfloat16(a);
            __nv_bfloat16 lo = __float2bfloat16(a - __bfloat162float(hi));
            int o = (oc * 9 + t9) * 2048 + ic0 + ic;
            g_wAh[o] = hi; g_wAl[o] = lo;
        }
    } else {
        __shared__ float sm_[32][197];
        const int r = blockIdx.x - 1024;
        const int b = r >> 6;
        const int ic0 = (r & 63) * 32;
        const float* src = rpn + ((size_t)b * 2048 + ic0) * 196;
        for (int i = threadIdx.x; i < 32 * 196; i += 256) {
            int ic = i / 196, p = i - ic * 196;
            sm_[ic][p] = src[ic * 196 + p];
        }
        __syncthreads();
        for (int i = threadIdx.x; i < 32 * 196; i += 256) {
            int p = i >> 5, ic = i & 31;
            float a = sm_[ic][p];
            __nv_bfloat16 hi = __float2bfloat16(a);
            __nv_bfloat16 lo = __float2bfloat16(a - __bfloat162float(hi));
            int o = (b * 196 + p) * 2048 + ic0 + ic;
            g_rTh[o] = hi; g_rTl[o] = lo;
        }
    }
}

// slot -> (tile, chunk range) mapping. tiles 0..8: 23 slots, tiles 9..12: 22 slots.
// tile work = 1152 k-chunks. 1152=23*50+2 -> 2 parts of 51, 21 of 50.
//                            1152=22*52+8 -> 8 parts of 53, 14 of 52.
__device__ __forceinline__ void slot_map(int c, int& T, int& a, int& len) {
    if (c < 207) {
        T = c / 23;
        int j = c - 23 * T;
        a = (j < 2) ? 51 * j : 50 * j + 2;
        len = (j < 2) ? 51 : 50;
    } else {
        int c2 = c - 207;
        int q = c2 / 22;
        T = 9 + q;
        int j = c2 - 22 * q;
        a = (j < 8) ? 53 * j : 52 * j + 8;
        len = (j < 8) ? 53 : 52;
    }
}

// ---------------- conv1 via wmma bf16 hi/lo split, balanced persistent slots ----------------
// grid 295, 256 thr (8 warps). CTA tile 128x128, warp tile 64x32, K chunk 16.
__global__ __launch_bounds__(256) void conv1_wmma() {
    extern __shared__ __nv_bfloat16 sm[];
    const int t = threadIdx.x;
    const int warp = t >> 5;
    int T, ka, klen;
    slot_map(blockIdx.x, T, ka, klen);
    const int nbase = T * 128;
    const int wm = (warp >> 2) * 64;
    const int wn = (warp & 3) * 32;

    wmma::fragment<wmma::accumulator, 16, 16, 16, float> acc[4][2];
#pragma unroll
    for (int m = 0; m < 4; ++m)
#pragma unroll
        for (int n = 0; n < 2; ++n) wmma::fill_fragment(acc[m][n], 0.f);

    int b_b[2], b_oy[2], b_ox[2]; bool b_v[2];
    int l_arr[2], l_row[2], l_half[2];
#pragma unroll
    for (int i = 0; i < 2; ++i) {
        int idx = i * 256 + t;
        l_arr[i] = idx >> 8; l_row[i] = (idx >> 1) & 127; l_half[i] = idx & 1;
        int px = nbase + l_row[i];
        bool v = px < GN;
        int pc = v ? px : 0;
        int bb = pc / 196, pp = pc - bb * 196;
        b_b[i] = bb; b_oy[i] = pp / 14; b_ox[i] = pp - 14 * (pp / 14); b_v[i] = v;
    }

    uint4 ra[2], rb[2];
    auto fetch = [&](int kc) {
        const int t9 = kc >> 7;
        const int icb = (kc & 127) << 4;
        const int ky = t9 / 3, kx = t9 - 3 * (t9 / 3);
#pragma unroll
        for (int i = 0; i < 2; ++i) {
            const __nv_bfloat16* srcA = (l_arr[i] ? g_wAl : g_wAh) +
                ((l_row[i] * 9 + t9) << 11) + icb + l_half[i] * 8;
            ra[i] = *(const uint4*)srcA;
            int iy = b_oy[i] + ky - 1, ix = b_ox[i] + kx - 1;
            bool inb = b_v[i] && ((unsigned)iy < 14u) && ((unsigned)ix < 14u);
            if (inb) {
                const __nv_bfloat16* srcB = (l_arr[i] ? g_rTl : g_rTh) +
                    ((b_b[i] * 196 + iy * 14 + ix) << 11) + icb + l_half[i] * 8;
                rb[i] = *(const uint4*)srcB;
            } else {
                rb[i] = make_uint4(0, 0, 0, 0);
            }
        }
    };
    auto store = [&](int buf) {
        __nv_bfloat16* bp = sm + buf * BUFS;
#pragma unroll
        for (int i = 0; i < 2; ++i) {
            *(uint4*)(bp + (l_arr[i] ? AL_O : AH_O) + l_row[i] * 24 + l_half[i] * 8) = ra[i];
            *(uint4*)(bp + (l_arr[i] ? BL_O : BH_O) + l_row[i] * 24 + l_half[i] * 8) = rb[i];
        }
    };

    fetch(ka);
    store(0);
    __syncthreads();

    for (int ch = 0; ch < klen; ++ch) {
        const int cur = ch & 1;
        const bool more = (ch + 1 < klen);
        if (more) fetch(ka + ch + 1);

        const __nv_bfloat16* bp = sm + cur * BUFS;
#pragma unroll
        for (int c = 0; c < 3; ++c) {
            const __nv_bfloat16* Ab = bp + (c == 2 ? AL_O : AH_O);
            const __nv_bfloat16* Bb = bp + (c == 1 ? BL_O : BH_O);
            wmma::fragment<wmma::matrix_b, 16, 16, 16, __nv_bfloat16, wmma::col_major> fb[2];
#pragma unroll
            for (int n = 0; n < 2; ++n)
                wmma::load_matrix_sync(fb[n], Bb + (wn + n * 16) * 24, 24);
#pragma unroll
            for (int m = 0; m < 4; ++m) {
                wmma::fragment<wmma::matrix_a, 16, 16, 16, __nv_bfloat16, wmma::row_major> fa;
                wmma::load_matrix_sync(fa, Ab + (wm + m * 16) * 24, 24);
                wmma::mma_sync(acc[m][0], fa, fb[0], acc[m][0]);
                wmma::mma_sync(acc[m][1], fa, fb[1], acc[m][1]);
            }
        }

        if (more) store(cur ^ 1);
        __syncthreads();
    }

    float* base = &g_part[blockIdx.x][0][0];
#pragma unroll
    for (int m = 0; m < 4; ++m)
#pragma unroll
        for (int n = 0; n < 2; ++n)
            wmma::store_matrix_sync(base + (wm + m * 16) * 128 + wn + n * 16,
                                    acc[m][n], 128, wmma::mem_row_major);
}

// sum slot partials + bias + relu -> g_d1 (float4 loads)
__global__ void reduce_relu_kernel(const float* __restrict__ bd1) {
    int i = blockIdx.x * 256 + threadIdx.x;
    if (i >= 128 * (GN / 4)) return;
    int oc = i / (GN / 4);
    int n0 = (i - oc * (GN / 4)) * 4;
    int T = n0 >> 7;
    int nn = n0 & 127;
    int s0 = (T < 9) ? 23 * T : 207 + 22 * (T - 9);
    int cnt = (T < 9) ? 23 : 22;
    float4 s = make_float4(0.f, 0.f, 0.f, 0.f);
    for (int k = 0; k < cnt; ++k) {
        float4 v = *(const float4*)&g_part[s0 + k][oc][nn];
        s.x += v.x; s.y += v.y; s.z += v.z; s.w += v.w;
    }
    float bias = bd1[oc];
    float vals[4] = {s.x + bias, s.y + bias, s.z + bias, s.w + bias};
#pragma unroll
    for (int j = 0; j < 4; ++j) {
        int n = n0 + j;
        int b = n / 196, p = n - b * 196;
        g_d1[b][oc][p] = fmaxf(vals[j], 0.f);
    }
}

// ---------------- conv2: grid (8 b, 32 ic-splits of 4, 2 oc-groups), 392 thr ----------------
__global__ __launch_bounds__(392) void conv2_part(const float* __restrict__ wd2) {
    __shared__ float ds[4][196];
    __shared__ float ws[4][64][9];
    const int b = blockIdx.x, sp = blockIdx.y, ocg = blockIdx.z;
    const int t = threadIdx.x;
    for (int i = t; i < 4 * 196; i += 392) {
        int ic = i / 196, p = i - ic * 196;
        ds[ic][p] = g_d1[b][sp * 4 + ic][p];
    }
    for (int i = t; i < 4 * 64 * 9; i += 392) {
        int ic = i / 576;
        int r = i - ic * 576;
        int oc = r / 9, k = r - oc * 9;
        ws[ic][oc][k] = wd2[(size_t)(ocg * 64 + oc) * 1152 + (sp * 4 + ic) * 9 + k];
    }
    __syncthreads();
    const int p = t % 49;
    const int g = t / 49;          // 0..7 -> 8 oc each
    const int oy = p / 7, ox = p - 7 * (p / 7);

    int off[9]; bool val[9];
#pragma unroll
    for (int ky = 0; ky < 3; ++ky)
#pragma unroll
        for (int kx = 0; kx < 3; ++kx) {
            int iy = 2 * oy - 1 + ky, ix = 2 * ox - 1 + kx;
            bool inb = ((unsigned)iy < 14u) && ((unsigned)ix < 14u);
            val[ky * 3 + kx] = inb;
            off[ky * 3 + kx] = inb ? iy * 14 + ix : 0;
        }

    float acc[8];
#pragma unroll
    for (int r = 0; r < 8; ++r) acc[r] = 0.f;
#pragma unroll
    for (int ic = 0; ic < 4; ++ic) {
        float d[9];
#pragma unroll
        for (int k = 0; k < 9; ++k) d[k] = val[k] ? ds[ic][off[k]] : 0.f;
#pragma unroll
        for (int r = 0; r < 8; ++r) {
            const float* w = &ws[ic][g * 8 + r][0];
            float a = acc[r];
#pragma unroll
            for (int k = 0; k < 9; ++k) a += w[k] * d[k];
            acc[r] = a;
        }
    }
#pragma unroll
    for (int r = 0; r < 8; ++r) g_p2[sp][b][ocg * 64 + g * 8 + r][p] = acc[r];
}

__global__ void conv2_reduce(const float* __restrict__ bd2) {
    int i = blockIdx.x * 256 + threadIdx.x;
    if (i >= BATCH * 128 * 49) return;
    int b = i / (128 * 49);
    int r = i - b * (128 * 49);
    int oc = r / 49, p = r - oc * 49;
    float s = bd2[oc];
#pragma unroll
    for (int sp = 0; sp < C2S; ++sp) s += g_p2[sp][b][oc][p];
    g_d2[b][oc][p] = fmaxf(s, 0.f);
}

// ---------------- conv3: grid (8 b, 32 ic-splits of 4, 2 oc-groups), 128 thr ----------------
__global__ __launch_bounds__(128) void conv3_part(const float* __restrict__ wd3) {
    __shared__ float ds[4][49];
    __shared__ float ws[4][64][9];
    const int b = blockIdx.x, sp = blockIdx.y, ocg = blockIdx.z;
    const int t = threadIdx.x;
    for (int i = t; i < 4 * 49; i += 128) {
        int ic = i / 49, p = i - ic * 49;
        ds[ic][p] = g_d2[b][sp * 4 + ic][p];
    }
    for (int i = t; i < 4 * 64 * 9; i += 128) {
        int ic = i / 576;
        int r = i - ic * 576;
        int oc = r / 9, k = r - oc * 9;
        ws[ic][oc][k] = wd3[(size_t)(ocg * 64 + oc) * 1152 + (sp * 4 + ic) * 9 + k];
    }
    __syncthreads();
    const int p = t & 15;
    const int g = t >> 4;          // 0..7 -> 8 oc each
    const int oy = p >> 2, ox = p & 3;

    int off[9]; bool val[9];
#pragma unroll
    for (int ky = 0; ky < 3; ++ky)
#pragma unroll
        for (int kx = 0; kx < 3; ++kx) {
            int iy = 2 * oy - 1 + ky, ix = 2 * ox - 1 + kx;
            bool inb = ((unsigned)iy < 7u) && ((unsigned)ix < 7u);
            val[ky * 3 + kx] = inb;
            off[ky * 3 + kx] = inb ? iy * 7 + ix : 0;
        }

    float acc[8];
#pragma unroll
    for (int r = 0; r < 8; ++r) acc[r] = 0.f;
#pragma unroll
    for (int ic = 0; ic < 4; ++ic) {
        float d[9];
#pragma unroll
        for (int k = 0; k < 9; ++k) d[k] = val[k] ? ds[ic][off[k]] : 0.f;
#pragma unroll
        for (int r = 0; r < 8; ++r) {
            const float* w = &ws[ic][g * 8 + r][0];
            float a = acc[r];
#pragma unroll
            for (int k = 0; k < 9; ++k) a += w[k] * d[k];
            acc[r] = a;
        }
    }
#pragma unroll
    for (int r = 0; r < 8; ++r) g_p3[sp][b][ocg * 64 + g * 8 + r][p] = acc[r];
}

__global__ void conv3_reduce(const float* __restrict__ bd3) {
    int i = blockIdx.x * 256 + threadIdx.x;
    if (i >= BATCH * 128 * 16) return;
    int b = i / (128 * 16);
    int r = i - b * (128 * 16);
    int oc = r / 16, p = r & 15;
    float s = bd3[oc];
#pragma unroll
    for (int sp = 0; sp < C3S; ++sp) s += g_p3[sp][b][oc][p];
    g_d3[b][oc][p] = fmaxf(s, 0.f);
}

// ---------------- heads ----------------
__global__ void heads_kernel(const float* __restrict__ wt1, const float* __restrict__ bt1,
                             const float* __restrict__ wt2, const float* __restrict__ bt2,
                             const float* __restrict__ wt3, const float* __restrict__ bt3) {
    int b = blockIdx.x;
    int a = blockIdx.y * 256 + threadIdx.x;
    if (a >= NA) return;
    float acc;
    if (a < 1176) {
        int c = a / 196, p = a - c * 196;
        acc = bt1[c];
        const float* w = wt1 + c * 128;
        for (int ic = 0; ic < 128; ++ic) acc += g_d1[b][ic][p] * w[ic];
    } else if (a < 1470) {
        int a2 = a - 1176;
        int c = a2 / 49, p = a2 - c * 49;
        acc = bt2[c];
        const float* w = wt2 + c * 128;
        for (int ic = 0; ic < 128; ++ic) acc += g_d2[b][ic][p] * w[ic];
    } else {
        int a3 = a - 1470;
        int c = a3 / 16, p = a3 & 15;
        acc = bt3[c];
        const float* w = wt3 + c * 128;
        for (int ic = 0; ic < 128; ++ic) acc += g_d3[b][ic][p] * w[ic];
    }
    g_scores[b][a] = acc;
}

// ---------------- NMS + top-6 ----------------
__global__ __launch_bounds__(1024) void nms_topk_kernel(const float* __restrict__ anchors,
                                                        float* __restrict__ out) {
    __shared__ unsigned long long key[2048];
    const int b = blockIdx.x;
    const int tid = threadIdx.x;

    for (int a = tid; a < 2048; a += 1024) {
        unsigned long long k = 0ull;
        if (a < NA) {
            unsigned u = __float_as_uint(g_scores[b][a]);
            unsigned us = (u & 0x80000000u) ? ~u : (u | 0x80000000u);
            k = ((unsigned long long)us << 32) | (unsigned)(~(unsigned)a);
        }
        key[a] = k;
    }
    for (int kk = 2; kk <= 2048; kk <<= 1) {
        for (int j = kk >> 1; j > 0; j >>= 1) {
            __syncthreads();
            for (int i = tid; i < 2048; i += 1024) {
                int ixj = i ^ j;
                if (ixj > i) {
                    unsigned long long x = key[i], y = key[ixj];
                    bool desc = ((i & kk) == 0);
                    if (desc ? (x < y) : (x > y)) { key[i] = y; key[ixj] = x; }
                }
            }
        }
    }
    __syncthreads();

    if (tid == 0) {
        float ky0[TOPN], kx0[TOPN], ky1[TOPN], kx1[TOPN], karea[TOPN], kprob[TOPN];
        int kidx[TOPN];
        int nk = 0;
        for (int r = 0; r < NA && nk < TOPN; ++r) {
            unsigned long long k = key[r];
            int idx = (int)(~(unsigned)k);
            if (idx >= NA) break;
            float y0 = anchors[idx * 4 + 0], x0 = anchors[idx * 4 + 1];
            float y1 = anchors[idx * 4 + 2], x1 = anchors[idx * 4 + 3];
            float area = (y1 - y0) * (x1 - x0);
            bool sup = false;
            for (int s = 0; s < nk; ++s) {
                float ih = fminf(y1, ky1[s]) - fmaxf(y0, ky0[s]); if (ih < 0.f) ih = 0.f;
                float iw = fminf(x1, kx1[s]) - fmaxf(x0, kx0[s]); if (iw < 0.f) iw = 0.f;
                float inter = ih * iw;
                if (inter > 0.25f * (area + karea[s] - inter)) { sup = true; break; }
            }
            if (!sup) {
                unsigned us = (unsigned)(k >> 32);
                unsigned u = (us & 0x80000000u) ? (us ^ 0x80000000u) : ~us;
                ky0[nk] = y0; kx0[nk] = x0; ky1[nk] = y1; kx1[nk] = x1;
                karea[nk] = area; kidx[nk] = idx; kprob[nk] = __uint_as_float(u);
                ++nk;
            }
        }
        int fi = 0;
        while (nk < TOPN) {
            bool used = false;
            for (int s = 0; s < nk; ++s) if (kidx[s] == fi) used = true;
            if (!used) {
                ky0[nk] = anchors[fi * 4 + 0]; kx0[nk] = anchors[fi * 4 + 1];
                ky1[nk] = anchors[fi * 4 + 2]; kx1[nk] = anchors[fi * 4 + 3];
                karea[nk] = 0.f; kidx[nk] = fi; kprob[nk] = -INFINITY;
                ++nk;
            }
            ++fi;
        }
        for (int s = 0; s < TOPN; ++s) {
            int o = b * TOPN + s;
            g_boxes[b][s][0] = (int)kx0[s];
            g_boxes[b][s][1] = (int)ky0[s];
            g_boxes[b][s][2] = (int)kx1[s];
            g_boxes[b][s][3] = (int)ky1[s];
            out[OFF_COORDS + o * 4 + 0] = kx0[s];
            out[OFF_COORDS + o * 4 + 1] = ky0[s];
            out[OFF_COORDS + o * 4 + 2] = kx1[s];
            out[OFF_COORDS + o * 4 + 3] = ky1[s];
            out[OFF_PROB + o] = kprob[s];
            out[OFF_IDX + o] = (float)kidx[s];
        }
    }
}

// ---------------- crop-resize: 4 rows/block, float4 stores ----------------
__global__ __launch_bounds__(224) void crop_kernel(const float* __restrict__ xin,
                                                   float* __restrict__ out) {
    const int t  = threadIdx.x;
    const int xq = (t % 56) * 4;
    const int oy = blockIdx.x * 4 + t / 56;
    const int c  = blockIdx.y;
    const int bs = blockIdx.z;
    const int b  = bs / TOPN;
    const int s  = bs - b * TOPN;

    const int X0 = g_boxes[b][s][0], Y0 = g_boxes[b][s][1];
    const int X1 = g_boxes[b][s][2], Y1 = g_boxes[b][s][3];

    float ty = __fdiv_rn((float)oy, 223.0f);
    float sy = __fadd_rn((float)Y0, __fmul_rn(ty, (float)(Y1 - 1 - Y0)));
    int y0i = (int)floorf(sy);
    int y1i = min(y0i + 1, Y1 - 1);
    float wy = __fadd_rn(sy, -(float)y0i);

    const float* img = xin + ((size_t)b * 3 + c) * 448 * 448;
    auto fetch = [&](int y, int x) -> float {
        y -= 224; x -= 224;
        if ((unsigned)y < 448u && (unsigned)x < 448u) return img[y * 448 + x];
        return 0.f;
    };

    float4 res;
    float* rp = &res.x;
#pragma unroll
    for (int j = 0; j < 4; ++j) {
        int ox = xq + j;
        float tx = __fdiv_rn((float)ox, 223.0f);
        float sx = __fadd_rn((float)X0, __fmul_rn(tx, (float)(X1 - 1 - X0)));
        int x0i = (int)floorf(sx);
        int x1i = min(x0i + 1, X1 - 1);
        float wx = __fadd_rn(sx, -(float)x0i);

        float f00 = fetch(y0i, x0i), f01 = fetch(y0i, x1i);
        float f10 = fetch(y1i, x0i), f11 = fetch(y1i, x1i);
        float top = (1.f - wx) * f00 + wx * f01;
        float bot = (1.f - wx) * f10 + wx * f11;
        rp[j] = (1.f - wy) * top + wy * bot;
    }
    *(float4*)&out[(((size_t)bs * 3 + c) * OUTP + oy) * OUTP + xq] = res;
}

// ---------------- launch ----------------
extern "C" void kernel_launch(void* const* d_in, const int* in_sizes, int n_in,
                              void* d_out, int out_size) {
    const float* x       = (const float*)d_in[0];
    const float* rpn     = (const float*)d_in[1];
    const float* anchors = (const float*)d_in[2];
    const float* wd1 = (const float*)d_in[3];
    const float* bd1 = (const float*)d_in[4];
    const float* wd2 = (const float*)d_in[5];
    const float* bd2 = (const float*)d_in[6];
    const float* wd3 = (const float*)d_in[7];
    const float* bd3 = (const float*)d_in[8];
    const float* wt1 = (const float*)d_in[9];
    const float* bt1 = (const float*)d_in[10];
    const float* wt2 = (const float*)d_in[11];
    const float* bt2 = (const float*)d_in[12];
    const float* wt3 = (const float*)d_in[13];
    const float* bt3 = (const float*)d_in[14];
    float* out = (float*)d_out;

    prep_all<<<1536, 256>>>(wd1, rpn);
    conv1_wmma<<<NSLOT, 256, DYNSMEM>>>();
    reduce_relu_kernel<<<(128 * (GN / 4) + 255) / 256, 256>>>(bd1);
    conv2_part<<<dim3(BATCH, C2S, 2), 392>>>(wd2);
    conv2_reduce<<<(BATCH * 128 * 49 + 255) / 256, 256>>>(bd2);
    conv3_part<<<dim3(BATCH, C3S, 2), 128>>>(wd3);
    conv3_reduce<<<(BATCH * 128 * 16 + 255) / 256, 256>>>(bd3);
    heads_kernel<<<dim3(BATCH, 7), 256>>>(wt1, bt1, wt2, bt2, wt3, bt3);
    nms_topk_kernel<<<BATCH, 1024>>>(anchors, out);
    crop_kernel<<<dim3(56, 3, BATCH * TOPN), 224>>>(x, out);
}

// round 10
// speedup vs baseline: 1.2542x; 1.0389x over previous
#include <cuda_runtime.h>
#include <cuda_bf16.h>
#include <mma.h>
#include <math.h>
#include <stdint.h>

using namespace nvcuda;

// ---------------- problem constants ----------------
#define BATCH 8
#define NA    1614
#define TOPN  6
#define OUTP  224
#define GN    1568              // 8*196 px
#define GK    18432             // 2048*9
#define NSLOT 295               // conv1 slots (23*9 + 22*4)
#define NS2   72                // conv2 slots (4 tiles * 18)
#define NS3   36                // conv3 slots (1 tile * 36)

#define OFF_COORDS 7225344
#define OFF_PROB   7225536
#define OFF_IDX    7225584

// smem element offsets (bf16 elems), ldm 24 (16 used + 8 pad)
#define BUFS  12288
#define DYNSMEM (2 * BUFS * 2)      // 49152 bytes

// ---------------- scratch globals ----------------
__device__ __nv_bfloat16 g_wAh[128 * GK];         // conv1 W [oc][t9*2048+ic] hi
__device__ __nv_bfloat16 g_wAl[128 * GK];
__device__ __nv_bfloat16 g_w2h[128 * 1152];       // conv2 W [oc][t9*128+ic]
__device__ __nv_bfloat16 g_w2l[128 * 1152];
__device__ __nv_bfloat16 g_w3h[128 * 1152];
__device__ __nv_bfloat16 g_w3l[128 * 1152];
__device__ __nv_bfloat16 g_rTh[8 * 196 * 2048];   // rpn NHWC hi
__device__ __nv_bfloat16 g_rTl[8 * 196 * 2048];
__device__ __nv_bfloat16 g_d1h[8 * 196 * 128];    // d1 NHWC bf16
__device__ __nv_bfloat16 g_d1l[8 * 196 * 128];
__device__ __nv_bfloat16 g_d2h[8 * 49 * 128];
__device__ __nv_bfloat16 g_d2l[8 * 49 * 128];
__device__ float g_part[NSLOT][128][128];
__device__ float g_p2w[NS2][128][128];
__device__ float g_p3w[NS3][128][128];
__device__ float g_d1[BATCH][128][196];
__device__ float g_d2[BATCH][128][49];
__device__ float g_d3[BATCH][128][16];
__device__ float g_scores[BATCH][NA];
__device__ int   g_boxes[BATCH][TOPN][4];

// ---------------- helpers ----------------
__device__ __forceinline__ uint32_t smem_u32(const void* p) {
    uint32_t a;
    asm("{ .reg .u64 tmp; cvta.to.shared.u64 tmp, %1; cvt.u32.u64 %0, tmp; }" : "=r"(a) : "l"(p));
    return a;
}
__device__ __forceinline__ void cp16(uint32_t dst, const void* src, bool pred) {
    int sz = pred ? 16 : 0;
    asm volatile("cp.async.cg.shared.global [%0], [%1], 16, %2;" :: "r"(dst), "l"(src), "r"(sz));
}
#define CP_COMMIT() asm volatile("cp.async.commit_group;" ::: "memory")
#define CP_WAIT0()  asm volatile("cp.async.wait_group 0;" ::: "memory")
#define CP_WAIT1()  asm volatile("cp.async.wait_group 1;" ::: "memory")

__device__ __forceinline__ void split_bf16(float a, __nv_bfloat16& hi, __nv_bfloat16& lo) {
    hi = __float2bfloat16(a);
    lo = __float2bfloat16(a - __bfloat162float(hi));
}

// ---------------- merged prep ----------------
// blocks [0,1024) wd1, [1024,1536) rpn, [1536,1664) wd2, [1664,1792) wd3
__global__ __launch_bounds__(256) void prep_all(const float* __restrict__ wd1,
                                                const float* __restrict__ rpn,
                                                const float* __restrict__ wd2,
                                                const float* __restrict__ wd3) {
    const int bx = blockIdx.x;
    if (bx < 1024) {
        __shared__ float w[2304];
        const int oc = bx >> 3;
        const int ic0 = (bx & 7) * 256;
        const float* src = wd1 + (size_t)oc * GK + (size_t)ic0 * 9;
        for (int i = threadIdx.x; i < 2304; i += 256) w[i] = src[i];
        __syncthreads();
        for (int i = threadIdx.x; i < 2304; i += 256) {
            int t9 = i >> 8, ic = i & 255;
            __nv_bfloat16 hi, lo; split_bf16(w[ic * 9 + t9], hi, lo);
            int o = oc * GK + t9 * 2048 + ic0 + ic;
            g_wAh[o] = hi; g_wAl[o] = lo;
        }
    } else if (bx < 1536) {
        __shared__ float sm_[32][197];
        const int r = bx - 1024;
        const int b = r >> 6;
        const int ic0 = (r & 63) * 32;
        const float* src = rpn + ((size_t)b * 2048 + ic0) * 196;
        for (int i = threadIdx.x; i < 32 * 196; i += 256) {
            int ic = i / 196, p = i - ic * 196;
            sm_[ic][p] = src[ic * 196 + p];
        }
        __syncthreads();
        for (int i = threadIdx.x; i < 32 * 196; i += 256) {
            int p = i >> 5, ic = i & 31;
            __nv_bfloat16 hi, lo; split_bf16(sm_[ic][p], hi, lo);
            int o = (b * 196 + p) * 2048 + ic0 + ic;
            g_rTh[o] = hi; g_rTl[o] = lo;
        }
    } else {
        const bool is3 = (bx >= 1664);
        const int oc = bx - (is3 ? 1664 : 1536);
        const float* src = (is3 ? wd3 : wd2) + (size_t)oc * 1152;
        __nv_bfloat16* dh = (is3 ? g_w3h : g_w2h) + oc * 1152;
        __nv_bfloat16* dl = (is3 ? g_w3l : g_w2l) + oc * 1152;
        for (int o = threadIdx.x; o < 1152; o += 256) {
            int t9 = o >> 7, ic = o & 127;
            __nv_bfloat16 hi, lo; split_bf16(src[ic * 9 + t9], hi, lo);
            dh[o] = hi; dl[o] = lo;
        }
    }
}

// slot -> (tile, chunk range) for conv1
__device__ __forceinline__ void slot_map(int c, int& T, int& a, int& len) {
    if (c < 207) {
        T = c / 23;
        int j = c - 23 * T;
        a = (j < 2) ? 51 * j : 50 * j + 2;
        len = (j < 2) ? 51 : 50;
    } else {
        int c2 = c - 207;
        int q = c2 / 22;
        T = 9 + q;
        int j = c2 - 22 * q;
        a = (j < 8) ? 53 * j : 52 * j + 8;
        len = (j < 8) ? 53 : 52;
    }
}

// ---------------- generic conv-as-GEMM via wmma bf16 hi/lo + cp.async ----------------
// 256 thr (8 warps), CTA tile M=128 x N=128, K chunk 16, warp tile 64x32.
template<int L>
__global__ __launch_bounds__(256) void conv_wmma() {
    extern __shared__ __nv_bfloat16 sm[];
    const uint32_t sb = smem_u32(sm);
    const int t = threadIdx.x;
    const int warp = t >> 5;

    int T, ka, klen;
    if (L == 1) { slot_map(blockIdx.x, T, ka, klen); }
    else if (L == 2) { T = blockIdx.x / 18; ka = (blockIdx.x % 18) * 4; klen = 4; }
    else { T = 0; ka = blockIdx.x * 2; klen = 2; }

    const int nbase = T * 128;
    const int wm = (warp >> 2) * 64;
    const int wn = (warp & 3) * 32;
    constexpr int KT = (L == 1) ? GK : 1152;
    constexpr int NREAL = (L == 1) ? GN : (L == 2 ? 392 : 128);

    const __nv_bfloat16* Ah = (L == 1) ? g_wAh : (L == 2) ? g_w2h : g_w3h;
    const __nv_bfloat16* Al = (L == 1) ? g_wAl : (L == 2) ? g_w2l : g_w3l;
    const __nv_bfloat16* Bh = (L == 1) ? g_rTh : (L == 2) ? g_d1h : g_d2h;
    const __nv_bfloat16* Bl = (L == 1) ? g_rTl : (L == 2) ? g_d1l : g_d2l;

    wmma::fragment<wmma::accumulator, 16, 16, 16, float> acc[4][2];
#pragma unroll
    for (int m = 0; m < 4; ++m)
#pragma unroll
        for (int n = 0; n < 2; ++n) wmma::fill_fragment(acc[m][n], 0.f);

    int b_b[2], b_oy[2], b_ox[2]; bool b_v[2];
    int l_arr[2], l_row[2], l_half[2];
#pragma unroll
    for (int i = 0; i < 2; ++i) {
        int idx = i * 256 + t;
        l_arr[i] = idx >> 8; l_row[i] = (idx >> 1) & 127; l_half[i] = idx & 1;
        int px = nbase + l_row[i];
        bool v = px < NREAL;
        int pc = v ? px : 0;
        int bb, pp;
        if (L == 1) { bb = pc / 196; pp = pc - bb * 196; b_oy[i] = pp / 14; b_ox[i] = pp % 14; }
        else if (L == 2) { bb = pc / 49; pp = pc - bb * 49; b_oy[i] = pp / 7; b_ox[i] = pp % 7; }
        else { bb = pc >> 4; pp = pc & 15; b_oy[i] = pp >> 2; b_ox[i] = pp & 3; }
        b_b[i] = bb; b_v[i] = v;
    }

    auto issue = [&](int kc, int buf) {
        int t9, icb;
        if (L == 1) { t9 = kc >> 7; icb = (kc & 127) << 4; }
        else { t9 = kc >> 3; icb = (kc & 7) << 4; }
        const int ky = t9 / 3, kx = t9 - 3 * (t9 / 3);
        const uint32_t bbase = sb + buf * (BUFS * 2);
#pragma unroll
        for (int i = 0; i < 2; ++i) {
            const int rowoff = l_row[i] * 48 + l_half[i] * 16;
            // A
            const __nv_bfloat16* srcA = (l_arr[i] ? Al : Ah) + l_row[i] * KT + kc * 16 + l_half[i] * 8;
            cp16(bbase + l_arr[i] * 6144 + rowoff, srcA, true);
            // B (im2col row)
            int iy, ix, dimY, dimX;
            if (L == 1) { iy = b_oy[i] + ky - 1; ix = b_ox[i] + kx - 1; dimY = 14; dimX = 14; }
            else if (L == 2) { iy = 2 * b_oy[i] - 1 + ky; ix = 2 * b_ox[i] - 1 + kx; dimY = 14; dimX = 14; }
            else { iy = 2 * b_oy[i] - 1 + ky; ix = 2 * b_ox[i] - 1 + kx; dimY = 7; dimX = 7; }
            bool inb = b_v[i] && ((unsigned)iy < (unsigned)dimY) && ((unsigned)ix < (unsigned)dimX);
            int iyc = inb ? iy : 0, ixc = inb ? ix : 0;
            const __nv_bfloat16* srcB;
            if (L == 1)
                srcB = (l_arr[i] ? Bl : Bh) + ((b_b[i] * 196 + iyc * 14 + ixc) << 11) + icb + l_half[i] * 8;
            else if (L == 2)
                srcB = (l_arr[i] ? Bl : Bh) + ((b_b[i] * 196 + iyc * 14 + ixc) << 7) + icb + l_half[i] * 8;
            else
                srcB = (l_arr[i] ? Bl : Bh) + ((b_b[i] * 49 + iyc * 7 + ixc) << 7) + icb + l_half[i] * 8;
            cp16(bbase + 12288 + l_arr[i] * 6144 + rowoff, srcB, inb);
        }
    };

    issue(ka, 0);
    CP_COMMIT();

    for (int ch = 0; ch < klen; ++ch) {
        const int cur = ch & 1;
        const bool more = (ch + 1 < klen);
        if (more) { issue(ka + ch + 1, cur ^ 1); CP_COMMIT(); }
        if (more) { CP_WAIT1(); } else { CP_WAIT0(); }
        __syncthreads();

        const __nv_bfloat16* bp = sm + cur * BUFS;
#pragma unroll
        for (int c = 0; c < 3; ++c) {
            const __nv_bfloat16* Ab = bp + (c == 2 ? 3072 : 0);
            const __nv_bfloat16* Bb = bp + 6144 + (c == 1 ? 3072 : 0);
            wmma::fragment<wmma::matrix_b, 16, 16, 16, __nv_bfloat16, wmma::col_major> fb[2];
#pragma unroll
            for (int n = 0; n < 2; ++n)
                wmma::load_matrix_sync(fb[n], Bb + (wn + n * 16) * 24, 24);
#pragma unroll
            for (int m = 0; m < 4; ++m) {
                wmma::fragment<wmma::matrix_a, 16, 16, 16, __nv_bfloat16, wmma::row_major> fa;
                wmma::load_matrix_sync(fa, Ab + (wm + m * 16) * 24, 24);
                wmma::mma_sync(acc[m][0], fa, fb[0], acc[m][0]);
                wmma::mma_sync(acc[m][1], fa, fb[1], acc[m][1]);
            }
        }
        __syncthreads();
    }

    float* base = (L == 1) ? &g_part[blockIdx.x][0][0]
                : (L == 2) ? &g_p2w[blockIdx.x][0][0]
                           : &g_p3w[blockIdx.x][0][0];
#pragma unroll
    for (int m = 0; m < 4; ++m)
#pragma unroll
        for (int n = 0; n < 2; ++n)
            wmma::store_matrix_sync(base + (wm + m * 16) * 128 + wn + n * 16,
                                    acc[m][n], 128, wmma::mem_row_major);
}

// ---------------- reduce kernels ----------------
__global__ void reduce1(const float* __restrict__ bd1) {
    int i = blockIdx.x * 256 + threadIdx.x;
    if (i >= 128 * 392) return;
    int oc = i / 392;
    int n0 = (i - oc * 392) * 4;
    int T = n0 >> 7, nn = n0 & 127;
    int s0 = (T < 9) ? 23 * T : 207 + 22 * (T - 9);
    int cnt = (T < 9) ? 23 : 22;
    float4 s = make_float4(0.f, 0.f, 0.f, 0.f);
    for (int k = 0; k < cnt; ++k) {
        float4 v = *(const float4*)&g_part[s0 + k][oc][nn];
        s.x += v.x; s.y += v.y; s.z += v.z; s.w += v.w;
    }
    float bias = bd1[oc];
    float vals[4] = {s.x + bias, s.y + bias, s.z + bias, s.w + bias};
#pragma unroll
    for (int j = 0; j < 4; ++j) {
        int n = n0 + j;
        int b = n / 196, p = n - b * 196;
        float r = fmaxf(vals[j], 0.f);
        g_d1[b][oc][p] = r;
        __nv_bfloat16 hi, lo; split_bf16(r, hi, lo);
        g_d1h[(b * 196 + p) * 128 + oc] = hi;
        g_d1l[(b * 196 + p) * 128 + oc] = lo;
    }
}

__global__ void reduce2(const float* __restrict__ bd2) {
    int i = blockIdx.x * 256 + threadIdx.x;
    if (i >= 128 * 98) return;
    int oc = i / 98;
    int n0 = (i - oc * 98) * 4;
    int tile = n0 >> 7, col = n0 & 127;
    float4 s = make_float4(0.f, 0.f, 0.f, 0.f);
#pragma unroll
    for (int j = 0; j < 18; ++j) {
        float4 v = *(const float4*)&g_p2w[tile * 18 + j][oc][col];
        s.x += v.x; s.y += v.y; s.z += v.z; s.w += v.w;
    }
    float bias = bd2[oc];
    float vals[4] = {s.x + bias, s.y + bias, s.z + bias, s.w + bias};
#pragma unroll
    for (int j = 0; j < 4; ++j) {
        int px = n0 + j;
        int b = px / 49, p = px - b * 49;
        float r = fmaxf(vals[j], 0.f);
        g_d2[b][oc][p] = r;
        __nv_bfloat16 hi, lo; split_bf16(r, hi, lo);
        g_d2h[(b * 49 + p) * 128 + oc] = hi;
        g_d2l[(b * 49 + p) * 128 + oc] = lo;
    }
}

__global__ void reduce3(const float* __restrict__ bd3) {
    int i = blockIdx.x * 256 + threadIdx.x;
    if (i >= 128 * 32) return;
    int oc = i / 32;
    int n0 = (i - oc * 32) * 4;
    float4 s = make_float4(0.f, 0.f, 0.f, 0.f);
#pragma unroll
    for (int j = 0; j < 36; ++j) {
        float4 v = *(const float4*)&g_p3w[j][oc][n0];
        s.x += v.x; s.y += v.y; s.z += v.z; s.w += v.w;
    }
    float bias = bd3[oc];
    float vals[4] = {s.x + bias, s.y + bias, s.z + bias, s.w + bias};
#pragma unroll
    for (int j = 0; j < 4; ++j) {
        int px = n0 + j;
        int b = px >> 4, p = px & 15;
        g_d3[b][oc][p] = fmaxf(vals[j], 0.f);
    }
}

// ---------------- heads ----------------
__global__ void heads_kernel(const float* __restrict__ wt1, const float* __restrict__ bt1,
                             const float* __restrict__ wt2, const float* __restrict__ bt2,
                             const float* __restrict__ wt3, const float* __restrict__ bt3) {
    int b = blockIdx.x;
    int a = blockIdx.y * 256 + threadIdx.x;
    if (a >= NA) return;
    float acc;
    if (a < 1176) {
        int c = a / 196, p = a - c * 196;
        acc = bt1[c];
        const float* w = wt1 + c * 128;
        for (int ic = 0; ic < 128; ++ic) acc += g_d1[b][ic][p] * w[ic];
    } else if (a < 1470) {
        int a2 = a - 1176;
        int c = a2 / 49, p = a2 - c * 49;
        acc = bt2[c];
        const float* w = wt2 + c * 128;
        for (int ic = 0; ic < 128; ++ic) acc += g_d2[b][ic][p] * w[ic];
    } else {
        int a3 = a - 1470;
        int c = a3 / 16, p = a3 & 15;
        acc = bt3[c];
        const float* w = wt3 + c * 128;
        for (int ic = 0; ic < 128; ++ic) acc += g_d3[b][ic][p] * w[ic];
    }
    g_scores[b][a] = acc;
}

// ---------------- NMS + top-6 ----------------
__global__ __launch_bounds__(1024) void nms_topk_kernel(const float* __restrict__ anchors,
                                                        float* __restrict__ out) {
    __shared__ unsigned long long key[2048];
    const int b = blockIdx.x;
    const int tid = threadIdx.x;

    for (int a = tid; a < 2048; a += 1024) {
        unsigned long long k = 0ull;
        if (a < NA) {
            unsigned u = __float_as_uint(g_scores[b][a]);
            unsigned us = (u & 0x80000000u) ? ~u : (u | 0x80000000u);
            k = ((unsigned long long)us << 32) | (unsigned)(~(unsigned)a);
        }
        key[a] = k;
    }
    for (int kk = 2; kk <= 2048; kk <<= 1) {
        for (int j = kk >> 1; j > 0; j >>= 1) {
            __syncthreads();
            for (int i = tid; i < 2048; i += 1024) {
                int ixj = i ^ j;
                if (ixj > i) {
                    unsigned long long x = key[i], y = key[ixj];
                    bool desc = ((i & kk) == 0);
                    if (desc ? (x < y) : (x > y)) { key[i] = y; key[ixj] = x; }
                }
            }
        }
    }
    __syncthreads();

    if (tid == 0) {
        float ky0[TOPN], kx0[TOPN], ky1[TOPN], kx1[TOPN], karea[TOPN], kprob[TOPN];
        int kidx[TOPN];
        int nk = 0;
        for (int r = 0; r < NA && nk < TOPN; ++r) {
            unsigned long long k = key[r];
            int idx = (int)(~(unsigned)k);
            if (idx >= NA) break;
            float y0 = anchors[idx * 4 + 0], x0 = anchors[idx * 4 + 1];
            float y1 = anchors[idx * 4 + 2], x1 = anchors[idx * 4 + 3];
            float area = (y1 - y0) * (x1 - x0);
            bool sup = false;
            for (int s = 0; s < nk; ++s) {
                float ih = fminf(y1, ky1[s]) - fmaxf(y0, ky0[s]); if (ih < 0.f) ih = 0.f;
                float iw = fminf(x1, kx1[s]) - fmaxf(x0, kx0[s]); if (iw < 0.f) iw = 0.f;
                float inter = ih * iw;
                if (inter > 0.25f * (area + karea[s] - inter)) { sup = true; break; }
            }
            if (!sup) {
                unsigned us = (unsigned)(k >> 32);
                unsigned u = (us & 0x80000000u) ? (us ^ 0x80000000u) : ~us;
                ky0[nk] = y0; kx0[nk] = x0; ky1[nk] = y1; kx1[nk] = x1;
                karea[nk] = area; kidx[nk] = idx; kprob[nk] = __uint_as_float(u);
                ++nk;
            }
        }
        int fi = 0;
        while (nk < TOPN) {
            bool used = false;
            for (int s = 0; s < nk; ++s) if (kidx[s] == fi) used = true;
            if (!used) {
                ky0[nk] = anchors[fi * 4 + 0]; kx0[nk] = anchors[fi * 4 + 1];
                ky1[nk] = anchors[fi * 4 + 2]; kx1[nk] = anchors[fi * 4 + 3];
                karea[nk] = 0.f; kidx[nk] = fi; kprob[nk] = -INFINITY;
                ++nk;
            }
            ++fi;
        }
        for (int s = 0; s < TOPN; ++s) {
            int o = b * TOPN + s;
            g_boxes[b][s][0] = (int)kx0[s];
            g_boxes[b][s][1] = (int)ky0[s];
            g_boxes[b][s][2] = (int)kx1[s];
            g_boxes[b][s][3] = (int)ky1[s];
            out[OFF_COORDS + o * 4 + 0] = kx0[s];
            out[OFF_COORDS + o * 4 + 1] = ky0[s];
            out[OFF_COORDS + o * 4 + 2] = kx1[s];
            out[OFF_COORDS + o * 4 + 3] = ky1[s];
            out[OFF_PROB + o] = kprob[s];
            out[OFF_IDX + o] = (float)kidx[s];
        }
    }
}

// ---------------- crop-resize ----------------
__global__ __launch_bounds__(224) void crop_kernel(const float* __restrict__ xin,
                                                   float* __restrict__ out) {
    const int t  = threadIdx.x;
    const int xq = (t % 56) * 4;
    const int oy = blockIdx.x * 4 + t / 56;
    const int c  = blockIdx.y;
    const int bs = blockIdx.z;
    const int b  = bs / TOPN;
    const int s  = bs - b * TOPN;

    const int X0 = g_boxes[b][s][0], Y0 = g_boxes[b][s][1];
    const int X1 = g_boxes[b][s][2], Y1 = g_boxes[b][s][3];

    float ty = __fdiv_rn((float)oy, 223.0f);
    float sy = __fadd_rn((float)Y0, __fmul_rn(ty, (float)(Y1 - 1 - Y0)));
    int y0i = (int)floorf(sy);
    int y1i = min(y0i + 1, Y1 - 1);
    float wy = __fadd_rn(sy, -(float)y0i);

    const float* img = xin + ((size_t)b * 3 + c) * 448 * 448;
    auto fetch = [&](int y, int x) -> float {
        y -= 224; x -= 224;
        if ((unsigned)y < 448u && (unsigned)x < 448u) return img[y * 448 + x];
        return 0.f;
    };

    float4 res;
    float* rp = &res.x;
#pragma unroll
    for (int j = 0; j < 4; ++j) {
        int ox = xq + j;
        float tx = __fdiv_rn((float)ox, 223.0f);
        float sx = __fadd_rn((float)X0, __fmul_rn(tx, (float)(X1 - 1 - X0)));
        int x0i = (int)floorf(sx);
        int x1i = min(x0i + 1, X1 - 1);
        float wx = __fadd_rn(sx, -(float)x0i);

        float f00 = fetch(y0i, x0i), f01 = fetch(y0i, x1i);
        float f10 = fetch(y1i, x0i), f11 = fetch(y1i, x1i);
        float top = (1.f - wx) * f00 + wx * f01;
        float bot = (1.f - wx) * f10 + wx * f11;
        rp[j] = (1.f - wy) * top + wy * bot;
    }
    *(float4*)&out[(((size_t)bs * 3 + c) * OUTP + oy) * OUTP + xq] = res;
}

// ---------------- launch ----------------
extern "C" void kernel_launch(void* const* d_in, const int* in_sizes, int n_in,
                              void* d_out, int out_size) {
    const float* x       = (const float*)d_in[0];
    const float* rpn     = (const float*)d_in[1];
    const float* anchors = (const float*)d_in[2];
    const float* wd1 = (const float*)d_in[3];
    const float* bd1 = (const float*)d_in[4];
    const float* wd2 = (const float*)d_in[5];
    const float* bd2 = (const float*)d_in[6];
    const float* wd3 = (const float*)d_in[7];
    const float* bd3 = (const float*)d_in[8];
    const float* wt1 = (const float*)d_in[9];
    const float* bt1 = (const float*)d_in[10];
    const float* wt2 = (const float*)d_in[11];
    const float* bt2 = (const float*)d_in[12];
    const float* wt3 = (const float*)d_in[13];
    const float* bt3 = (const float*)d_in[14];
    float* out = (float*)d_out;

    prep_all<<<1792, 256>>>(wd1, rpn, wd2, wd3);
    conv_wmma<1><<<NSLOT, 256, DYNSMEM>>>();
    reduce1<<<(128 * 392 + 255) / 256, 256>>>(bd1);
    conv_wmma<2><<<NS2, 256, DYNSMEM>>>();
    reduce2<<<(128 * 98 + 255) / 256, 256>>>(bd2);
    conv_wmma<3><<<NS3, 256, DYNSMEM>>>();
    reduce3<<<(128 * 32 + 255) / 256, 256>>>(bd3);
    heads_kernel<<<dim3(BATCH, 7), 256>>>(wt1, bt1, wt2, bt2, wt3, bt3);
    nms_topk_kernel<<<BATCH, 1024>>>(anchors, out);
    crop_kernel<<<dim3(56, 3, BATCH * TOPN), 224>>>(x, out);
}

// round 11
// speedup vs baseline: 1.2579x; 1.0030x over previous
#include <cuda_runtime.h>
#include <cuda_bf16.h>
#include <mma.h>
#include <math.h>
#include <stdint.h>

using namespace nvcuda;

// ---------------- problem constants ----------------
#define BATCH 8
#define NA    1614
#define TOPN  6
#define OUTP  224
#define GN    1568              // 8*196 px
#define GK    18432             // 2048*9
#define NSLOT 295               // conv1 slots: 22 ranges x 13 tiles + 9 extra
#define NS2   72                // conv2 slots (18 ranges x 4 tiles)
#define NS3   36                // conv3 slots (1 tile x 36)

#define OFF_COORDS 7225344
#define OFF_PROB   7225536
#define OFF_IDX    7225584

// smem: 4 pipeline stages x 12288 bf16 (24KB) = 96KB
#define STG_ELEM 12288
#define DYNSMEM  (4 * STG_ELEM * 2)   // 98304 bytes

// ---------------- scratch globals ----------------
__device__ __nv_bfloat16 g_wAh[128 * GK];
__device__ __nv_bfloat16 g_wAl[128 * GK];
__device__ __nv_bfloat16 g_w2h[128 * 1152];
__device__ __nv_bfloat16 g_w2l[128 * 1152];
__device__ __nv_bfloat16 g_w3h[128 * 1152];
__device__ __nv_bfloat16 g_w3l[128 * 1152];
__device__ __nv_bfloat16 g_rTh[8 * 196 * 2048];
__device__ __nv_bfloat16 g_rTl[8 * 196 * 2048];
__device__ __nv_bfloat16 g_d1h[8 * 196 * 128];
__device__ __nv_bfloat16 g_d1l[8 * 196 * 128];
__device__ __nv_bfloat16 g_d2h[8 * 49 * 128];
__device__ __nv_bfloat16 g_d2l[8 * 49 * 128];
__device__ float g_part[NSLOT][128][128];
__device__ float g_p2w[NS2][128][128];
__device__ float g_p3w[NS3][128][128];
__device__ float g_d1[BATCH][128][196];
__device__ float g_d2[BATCH][128][49];
__device__ float g_d3[BATCH][128][16];
__device__ float g_scores[BATCH][NA];
__device__ int   g_boxes[BATCH][TOPN][4];

// ---------------- helpers ----------------
__device__ __forceinline__ uint32_t smem_u32(const void* p) {
    uint32_t a;
    asm("{ .reg .u64 tmp; cvta.to.shared.u64 tmp, %1; cvt.u32.u64 %0, tmp; }" : "=r"(a) : "l"(p));
    return a;
}
__device__ __forceinline__ void cp16(uint32_t dst, const void* src, bool pred) {
    int sz = pred ? 16 : 0;
    asm volatile("cp.async.cg.shared.global [%0], [%1], 16, %2;" :: "r"(dst), "l"(src), "r"(sz));
}
#define CP_COMMIT() asm volatile("cp.async.commit_group;" ::: "memory")
#define CP_WAIT3()  asm volatile("cp.async.wait_group 3;" ::: "memory")

__device__ __forceinline__ void split_bf16(float a, __nv_bfloat16& hi, __nv_bfloat16& lo) {
    hi = __float2bfloat16(a);
    lo = __float2bfloat16(a - __bfloat162float(hi));
}

// ---------------- merged prep ----------------
__global__ __launch_bounds__(256) void prep_all(const float* __restrict__ wd1,
                                                const float* __restrict__ rpn,
                                                const float* __restrict__ wd2,
                                                const float* __restrict__ wd3) {
    const int bx = blockIdx.x;
    if (bx < 1024) {
        __shared__ float w[2304];
        const int oc = bx >> 3;
        const int ic0 = (bx & 7) * 256;
        const float* src = wd1 + (size_t)oc * GK + (size_t)ic0 * 9;
        for (int i = threadIdx.x; i < 2304; i += 256) w[i] = src[i];
        __syncthreads();
        for (int i = threadIdx.x; i < 2304; i += 256) {
            int t9 = i >> 8, ic = i & 255;
            __nv_bfloat16 hi, lo; split_bf16(w[ic * 9 + t9], hi, lo);
            int o = oc * GK + t9 * 2048 + ic0 + ic;
            g_wAh[o] = hi; g_wAl[o] = lo;
        }
    } else if (bx < 1536) {
        __shared__ float sm_[32][197];
        const int r = bx - 1024;
        const int b = r >> 6;
        const int ic0 = (r & 63) * 32;
        const float* src = rpn + ((size_t)b * 2048 + ic0) * 196;
        for (int i = threadIdx.x; i < 32 * 196; i += 256) {
            int ic = i / 196, p = i - ic * 196;
            sm_[ic][p] = src[ic * 196 + p];
        }
        __syncthreads();
        for (int i = threadIdx.x; i < 32 * 196; i += 256) {
            int p = i >> 5, ic = i & 31;
            __nv_bfloat16 hi, lo; split_bf16(sm_[ic][p], hi, lo);
            int o = (b * 196 + p) * 2048 + ic0 + ic;
            g_rTh[o] = hi; g_rTl[o] = lo;
        }
    } else {
        const bool is3 = (bx >= 1664);
        const int oc = bx - (is3 ? 1664 : 1536);
        const float* src = (is3 ? wd3 : wd2) + (size_t)oc * 1152;
        __nv_bfloat16* dh = (is3 ? g_w3h : g_w2h) + oc * 1152;
        __nv_bfloat16* dl = (is3 ? g_w3l : g_w2l) + oc * 1152;
        for (int o = threadIdx.x; o < 1152; o += 256) {
            int t9 = o >> 7, ic = o & 127;
            __nv_bfloat16 hi, lo; split_bf16(src[ic * 9 + t9], hi, lo);
            dh[o] = hi; dl[o] = lo;
        }
    }
}

// conv1 slot mapping, k-major: c = j*13 + T (j<22), c = 286+T (j=22, T<9)
__device__ __forceinline__ void slot_map(int c, int& T, int& a, int& len) {
    int j;
    if (c < 286) { j = c / 13; T = c - 13 * j; }
    else { j = 22; T = c - 286; }
    if (T < 9) { a = (j < 2) ? 51 * j : 50 * j + 2; len = (j < 2) ? 51 : 50; }
    else       { a = (j < 8) ? 53 * j : 52 * j + 8; len = (j < 8) ? 53 : 52; }
}
__device__ __forceinline__ int slot_id(int T, int j) {
    return (j < 22) ? j * 13 + T : 286 + T;
}

// ---------------- conv-as-GEMM: wmma bf16 hi/lo + 4-stage cp.async ----------------
template<int L>
__global__ __launch_bounds__(256) void conv_wmma() {
    extern __shared__ __nv_bfloat16 sm[];
    const uint32_t sb = smem_u32(sm);
    const int t = threadIdx.x;
    const int warp = t >> 5;

    int T, ka, klen;
    if (L == 1) { slot_map(blockIdx.x, T, ka, klen); }
    else if (L == 2) { T = blockIdx.x & 3; ka = (blockIdx.x >> 2) * 4; klen = 4; }
    else { T = 0; ka = blockIdx.x * 2; klen = 2; }

    const int nbase = T * 128;
    const int wm = (warp >> 2) * 64;
    const int wn = (warp & 3) * 32;
    constexpr int KT = (L == 1) ? GK : 1152;
    constexpr int NREAL = (L == 1) ? GN : (L == 2 ? 392 : 128);

    const __nv_bfloat16* Ah = (L == 1) ? g_wAh : (L == 2) ? g_w2h : g_w3h;
    const __nv_bfloat16* Al = (L == 1) ? g_wAl : (L == 2) ? g_w2l : g_w3l;
    const __nv_bfloat16* Bh = (L == 1) ? g_rTh : (L == 2) ? g_d1h : g_d2h;
    const __nv_bfloat16* Bl = (L == 1) ? g_rTl : (L == 2) ? g_d1l : g_d2l;

    wmma::fragment<wmma::accumulator, 16, 16, 16, float> acc[4][2];
#pragma unroll
    for (int m = 0; m < 4; ++m)
#pragma unroll
        for (int n = 0; n < 2; ++n) wmma::fill_fragment(acc[m][n], 0.f);

    int b_b[2], b_oy[2], b_ox[2]; bool b_v[2];
    int l_arr[2], l_row[2], l_half[2];
#pragma unroll
    for (int i = 0; i < 2; ++i) {
        int idx = i * 256 + t;
        l_arr[i] = idx >> 8; l_row[i] = (idx >> 1) & 127; l_half[i] = idx & 1;
        int px = nbase + l_row[i];
        bool v = px < NREAL;
        int pc = v ? px : 0;
        int bb, pp;
        if (L == 1) { bb = pc / 196; pp = pc - bb * 196; b_oy[i] = pp / 14; b_ox[i] = pp % 14; }
        else if (L == 2) { bb = pc / 49; pp = pc - bb * 49; b_oy[i] = pp / 7; b_ox[i] = pp % 7; }
        else { bb = pc >> 4; pp = pc & 15; b_oy[i] = pp >> 2; b_ox[i] = pp & 3; }
        b_b[i] = bb; b_v[i] = v;
    }

    auto issue = [&](int kc, int stage) {
        int t9, icb;
        if (L == 1) { t9 = kc >> 7; icb = (kc & 127) << 4; }
        else { t9 = kc >> 3; icb = (kc & 7) << 4; }
        const int ky = t9 / 3, kx = t9 - 3 * (t9 / 3);
        const uint32_t bbase = sb + stage * (STG_ELEM * 2);
#pragma unroll
        for (int i = 0; i < 2; ++i) {
            const int rowoff = l_row[i] * 48 + l_half[i] * 16;
            const __nv_bfloat16* srcA = (l_arr[i] ? Al : Ah) + l_row[i] * KT + kc * 16 + l_half[i] * 8;
            cp16(bbase + l_arr[i] * 6144 + rowoff, srcA, true);
            int iy, ix, dimY, dimX;
            if (L == 1) { iy = b_oy[i] + ky - 1; ix = b_ox[i] + kx - 1; dimY = 14; dimX = 14; }
            else if (L == 2) { iy = 2 * b_oy[i] - 1 + ky; ix = 2 * b_ox[i] - 1 + kx; dimY = 14; dimX = 14; }
            else { iy = 2 * b_oy[i] - 1 + ky; ix = 2 * b_ox[i] - 1 + kx; dimY = 7; dimX = 7; }
            bool inb = b_v[i] && ((unsigned)iy < (unsigned)dimY) && ((unsigned)ix < (unsigned)dimX);
            int iyc = inb ? iy : 0, ixc = inb ? ix : 0;
            const __nv_bfloat16* srcB;
            if (L == 1)
                srcB = (l_arr[i] ? Bl : Bh) + ((b_b[i] * 196 + iyc * 14 + ixc) << 11) + icb + l_half[i] * 8;
            else if (L == 2)
                srcB = (l_arr[i] ? Bl : Bh) + ((b_b[i] * 196 + iyc * 14 + ixc) << 7) + icb + l_half[i] * 8;
            else
                srcB = (l_arr[i] ? Bl : Bh) + ((b_b[i] * 49 + iyc * 7 + ixc) << 7) + icb + l_half[i] * 8;
            cp16(bbase + 12288 + l_arr[i] * 6144 + rowoff, srcB, inb);
        }
    };

    // prologue: 3 commit groups (some may be empty)
#pragma unroll
    for (int pf = 0; pf < 3; ++pf) {
        if (pf < klen) issue(ka + pf, pf);
        CP_COMMIT();
    }

    for (int ch = 0; ch < klen; ++ch) {
        const int nxt = ch + 3;
        if (nxt < klen) issue(ka + nxt, nxt & 3);
        CP_COMMIT();
        CP_WAIT3();
        __syncthreads();

        const __nv_bfloat16* bp = sm + (ch & 3) * STG_ELEM;
#pragma unroll
        for (int c = 0; c < 3; ++c) {
            const __nv_bfloat16* Ab = bp + (c == 2 ? 3072 : 0);
            const __nv_bfloat16* Bb = bp + 6144 + (c == 1 ? 3072 : 0);
            wmma::fragment<wmma::matrix_b, 16, 16, 16, __nv_bfloat16, wmma::col_major> fb[2];
#pragma unroll
            for (int n = 0; n < 2; ++n)
                wmma::load_matrix_sync(fb[n], Bb + (wn + n * 16) * 24, 24);
#pragma unroll
            for (int m = 0; m < 4; ++m) {
                wmma::fragment<wmma::matrix_a, 16, 16, 16, __nv_bfloat16, wmma::row_major> fa;
                wmma::load_matrix_sync(fa, Ab + (wm + m * 16) * 24, 24);
                wmma::mma_sync(acc[m][0], fa, fb[0], acc[m][0]);
                wmma::mma_sync(acc[m][1], fa, fb[1], acc[m][1]);
            }
        }
        __syncthreads();
    }

    float* base = (L == 1) ? &g_part[blockIdx.x][0][0]
                : (L == 2) ? &g_p2w[blockIdx.x][0][0]
                           : &g_p3w[blockIdx.x][0][0];
#pragma unroll
    for (int m = 0; m < 4; ++m)
#pragma unroll
        for (int n = 0; n < 2; ++n)
            wmma::store_matrix_sync(base + (wm + m * 16) * 128 + wn + n * 16,
                                    acc[m][n], 128, wmma::mem_row_major);
}

// ---------------- reduce kernels ----------------
__global__ void reduce1(const float* __restrict__ bd1) {
    int i = blockIdx.x * 256 + threadIdx.x;
    if (i >= 128 * 392) return;
    int oc = i / 392;
    int n0 = (i - oc * 392) * 4;
    int T = n0 >> 7, nn = n0 & 127;
    int cnt = (T < 9) ? 23 : 22;
    float4 s = make_float4(0.f, 0.f, 0.f, 0.f);
    for (int j = 0; j < cnt; ++j) {
        float4 v = *(const float4*)&g_part[slot_id(T, j)][oc][nn];
        s.x += v.x; s.y += v.y; s.z += v.z; s.w += v.w;
    }
    float bias = bd1[oc];
    float vals[4] = {s.x + bias, s.y + bias, s.z + bias, s.w + bias};
#pragma unroll
    for (int j = 0; j < 4; ++j) {
        int n = n0 + j;
        int b = n / 196, p = n - b * 196;
        float r = fmaxf(vals[j], 0.f);
        g_d1[b][oc][p] = r;
        __nv_bfloat16 hi, lo; split_bf16(r, hi, lo);
        g_d1h[(b * 196 + p) * 128 + oc] = hi;
        g_d1l[(b * 196 + p) * 128 + oc] = lo;
    }
}

__global__ void reduce2(const float* __restrict__ bd2) {
    int i = blockIdx.x * 256 + threadIdx.x;
    if (i >= 128 * 98) return;
    int oc = i / 98;
    int n0 = (i - oc * 98) * 4;
    int tile = n0 >> 7, col = n0 & 127;
    float4 s = make_float4(0.f, 0.f, 0.f, 0.f);
#pragma unroll
    for (int j = 0; j < 18; ++j) {
        float4 v = *(const float4*)&g_p2w[j * 4 + tile][oc][col];
        s.x += v.x; s.y += v.y; s.z += v.z; s.w += v.w;
    }
    float bias = bd2[oc];
    float vals[4] = {s.x + bias, s.y + bias, s.z + bias, s.w + bias};
#pragma unroll
    for (int j = 0; j < 4; ++j) {
        int px = n0 + j;
        int b = px / 49, p = px - b * 49;
        float r = fmaxf(vals[j], 0.f);
        g_d2[b][oc][p] = r;
        __nv_bfloat16 hi, lo; split_bf16(r, hi, lo);
        g_d2h[(b * 49 + p) * 128 + oc] = hi;
        g_d2l[(b * 49 + p) * 128 + oc] = lo;
    }
}

__global__ void reduce3(const float* __restrict__ bd3) {
    int i = blockIdx.x * 256 + threadIdx.x;
    if (i >= 128 * 32) return;
    int oc = i / 32;
    int n0 = (i - oc * 32) * 4;
    float4 s = make_float4(0.f, 0.f, 0.f, 0.f);
#pragma unroll
    for (int j = 0; j < 36; ++j) {
        float4 v = *(const float4*)&g_p3w[j][oc][n0];
        s.x += v.x; s.y += v.y; s.z += v.z; s.w += v.w;
    }
    float bias = bd3[oc];
    float vals[4] = {s.x + bias, s.y + bias, s.z + bias, s.w + bias};
#pragma unroll
    for (int j = 0; j < 4; ++j) {
        int px = n0 + j;
        int b = px >> 4, p = px & 15;
        g_d3[b][oc][p] = fmaxf(vals[j], 0.f);
    }
}

// ---------------- heads ----------------
__global__ void heads_kernel(const float* __restrict__ wt1, const float* __restrict__ bt1,
                             const float* __restrict__ wt2, const float* __restrict__ bt2,
                             const float* __restrict__ wt3, const float* __restrict__ bt3) {
    int b = blockIdx.x;
    int a = blockIdx.y * 256 + threadIdx.x;
    if (a >= NA) return;
    float acc;
    if (a < 1176) {
        int c = a / 196, p = a - c * 196;
        acc = bt1[c];
        const float* w = wt1 + c * 128;
        for (int ic = 0; ic < 128; ++ic) acc += g_d1[b][ic][p] * w[ic];
    } else if (a < 1470) {
        int a2 = a - 1176;
        int c = a2 / 49, p = a2 - c * 49;
        acc = bt2[c];
        const float* w = wt2 + c * 128;
        for (int ic = 0; ic < 128; ++ic) acc += g_d2[b][ic][p] * w[ic];
    } else {
        int a3 = a - 1470;
        int c = a3 / 16, p = a3 & 15;
        acc = bt3[c];
        const float* w = wt3 + c * 128;
        for (int ic = 0; ic < 128; ++ic) acc += g_d3[b][ic][p] * w[ic];
    }
    g_scores[b][a] = acc;
}

// ---------------- NMS + top-6 ----------------
__global__ __launch_bounds__(1024) void nms_topk_kernel(const float* __restrict__ anchors,
                                                        float* __restrict__ out) {
    __shared__ unsigned long long key[2048];
    const int b = blockIdx.x;
    const int tid = threadIdx.x;

    for (int a = tid; a < 2048; a += 1024) {
        unsigned long long k = 0ull;
        if (a < NA) {
            unsigned u = __float_as_uint(g_scores[b][a]);
            unsigned us = (u & 0x80000000u) ? ~u : (u | 0x80000000u);
            k = ((unsigned long long)us << 32) | (unsigned)(~(unsigned)a);
        }
        key[a] = k;
    }
    for (int kk = 2; kk <= 2048; kk <<= 1) {
        for (int j = kk >> 1; j > 0; j >>= 1) {
            __syncthreads();
            for (int i = tid; i < 2048; i += 1024) {
                int ixj = i ^ j;
                if (ixj > i) {
                    unsigned long long x = key[i], y = key[ixj];
                    bool desc = ((i & kk) == 0);
                    if (desc ? (x < y) : (x > y)) { key[i] = y; key[ixj] = x; }
                }
            }
        }
    }
    __syncthreads();

    if (tid == 0) {
        float ky0[TOPN], kx0[TOPN], ky1[TOPN], kx1[TOPN], karea[TOPN], kprob[TOPN];
        int kidx[TOPN];
        int nk = 0;
        for (int r = 0; r < NA && nk < TOPN; ++r) {
            unsigned long long k = key[r];
            int idx = (int)(~(unsigned)k);
            if (idx >= NA) break;
            float y0 = anchors[idx * 4 + 0], x0 = anchors[idx * 4 + 1];
            float y1 = anchors[idx * 4 + 2], x1 = anchors[idx * 4 + 3];
            float area = (y1 - y0) * (x1 - x0);
            bool sup = false;
            for (int s = 0; s < nk; ++s) {
                float ih = fminf(y1, ky1[s]) - fmaxf(y0, ky0[s]); if (ih < 0.f) ih = 0.f;
                float iw = fminf(x1, kx1[s]) - fmaxf(x0, kx0[s]); if (iw < 0.f) iw = 0.f;
                float inter = ih * iw;
                if (inter > 0.25f * (area + karea[s] - inter)) { sup = true; break; }
            }
            if (!sup) {
                unsigned us = (unsigned)(k >> 32);
                unsigned u = (us & 0x80000000u) ? (us ^ 0x80000000u) : ~us;
                ky0[nk] = y0; kx0[nk] = x0; ky1[nk] = y1; kx1[nk] = x1;
                karea[nk] = area; kidx[nk] = idx; kprob[nk] = __uint_as_float(u);
                ++nk;
            }
        }
        int fi = 0;
        while (nk < TOPN) {
            bool used = false;
            for (int s = 0; s < nk; ++s) if (kidx[s] == fi) used = true;
            if (!used) {
                ky0[nk] = anchors[fi * 4 + 0]; kx0[nk] = anchors[fi * 4 + 1];
                ky1[nk] = anchors[fi * 4 + 2]; kx1[nk] = anchors[fi * 4 + 3];
                karea[nk] = 0.f; kidx[nk] = fi; kprob[nk] = -INFINITY;
                ++nk;
            }
            ++fi;
        }
        for (int s = 0; s < TOPN; ++s) {
            int o = b * TOPN + s;
            g_boxes[b][s][0] = (int)kx0[s];
            g_boxes[b][s][1] = (int)ky0[s];
            g_boxes[b][s][2] = (int)kx1[s];
            g_boxes[b][s][3] = (int)ky1[s];
            out[OFF_COORDS + o * 4 + 0] = kx0[s];
            out[OFF_COORDS + o * 4 + 1] = ky0[s];
            out[OFF_COORDS + o * 4 + 2] = kx1[s];
            out[OFF_COORDS + o * 4 + 3] = ky1[s];
            out[OFF_PROB + o] = kprob[s];
            out[OFF_IDX + o] = (float)kidx[s];
        }
    }
}

// ---------------- crop-resize ----------------
__global__ __launch_bounds__(224) void crop_kernel(const float* __restrict__ xin,
                                                   float* __restrict__ out) {
    const int t  = threadIdx.x;
    const int xq = (t % 56) * 4;
    const int oy = blockIdx.x * 4 + t / 56;
    const int c  = blockIdx.y;
    const int bs = blockIdx.z;
    const int b  = bs / TOPN;
    const int s  = bs - b * TOPN;

    const int X0 = g_boxes[b][s][0], Y0 = g_boxes[b][s][1];
    const int X1 = g_boxes[b][s][2], Y1 = g_boxes[b][s][3];

    float ty = __fdiv_rn((float)oy, 223.0f);
    float sy = __fadd_rn((float)Y0, __fmul_rn(ty, (float)(Y1 - 1 - Y0)));
    int y0i = (int)floorf(sy);
    int y1i = min(y0i + 1, Y1 - 1);
    float wy = __fadd_rn(sy, -(float)y0i);

    const float* img = xin + ((size_t)b * 3 + c) * 448 * 448;
    auto fetch = [&](int y, int x) -> float {
        y -= 224; x -= 224;
        if ((unsigned)y < 448u && (unsigned)x < 448u) return img[y * 448 + x];
        return 0.f;
    };

    float4 res;
    float* rp = &res.x;
#pragma unroll
    for (int j = 0; j < 4; ++j) {
        int ox = xq + j;
        float tx = __fdiv_rn((float)ox, 223.0f);
        float sx = __fadd_rn((float)X0, __fmul_rn(tx, (float)(X1 - 1 - X0)));
        int x0i = (int)floorf(sx);
        int x1i = min(x0i + 1, X1 - 1);
        float wx = __fadd_rn(sx, -(float)x0i);

        float f00 = fetch(y0i, x0i), f01 = fetch(y0i, x1i);
        float f10 = fetch(y1i, x0i), f11 = fetch(y1i, x1i);
        float top = (1.f - wx) * f00 + wx * f01;
        float bot = (1.f - wx) * f10 + wx * f11;
        rp[j] = (1.f - wy) * top + wy * bot;
    }
    *(float4*)&out[(((size_t)bs * 3 + c) * OUTP + oy) * OUTP + xq] = res;
}

// ---------------- launch ----------------
extern "C" void kernel_launch(void* const* d_in, const int* in_sizes, int n_in,
                              void* d_out, int out_size) {
    const float* x       = (const float*)d_in[0];
    const float* rpn     = (const float*)d_in[1];
    const float* anchors = (const float*)d_in[2];
    const float* wd1 = (const float*)d_in[3];
    const float* bd1 = (const float*)d_in[4];
    const float* wd2 = (const float*)d_in[5];
    const float* bd2 = (const float*)d_in[6];
    const float* wd3 = (const float*)d_in[7];
    const float* bd3 = (const float*)d_in[8];
    const float* wt1 = (const float*)d_in[9];
    const float* bt1 = (const float*)d_in[10];
    const float* wt2 = (const float*)d_in[11];
    const float* bt2 = (const float*)d_in[12];
    const float* wt3 = (const float*)d_in[13];
    const float* bt3 = (const float*)d_in[14];
    float* out = (float*)d_out;

    cudaFuncSetAttribute(conv_wmma<1>, cudaFuncAttributeMaxDynamicSharedMemorySize, DYNSMEM);
    cudaFuncSetAttribute(conv_wmma<2>, cudaFuncAttributeMaxDynamicSharedMemorySize, DYNSMEM);
    cudaFuncSetAttribute(conv_wmma<3>, cudaFuncAttributeMaxDynamicSharedMemorySize, DYNSMEM);

    prep_all<<<1792, 256>>>(wd1, rpn, wd2, wd3);
    conv_wmma<1><<<NSLOT, 256, DYNSMEM>>>();
    reduce1<<<(128 * 392 + 255) / 256, 256>>>(bd1);
    conv_wmma<2><<<NS2, 256, DYNSMEM>>>();
    reduce2<<<(128 * 98 + 255) / 256, 256>>>(bd2);
    conv_wmma<3><<<NS3, 256, DYNSMEM>>>();
    reduce3<<<(128 * 32 + 255) / 256, 256>>>(bd3);
    heads_kernel<<<dim3(BATCH, 7), 256>>>(wt1, bt1, wt2, bt2, wt3, bt3);
    nms_topk_kernel<<<BATCH, 1024>>>(anchors, out);
    crop_kernel<<<dim3(56, 3, BATCH * TOPN), 224>>>(x, out);
}